// round 1
// baseline (speedup 1.0000x reference)
#include <cuda_runtime.h>

// NeuroselectiveLinear: out[..., out_idx] = gather(x, in_idx) @ W^T + b
// x: [8192, 4096] f32   W: [1024, 1024] f32 (row = out feature, col = active in feature)
// b: [1024] f32   in_idx/out_idx: [1024] i32 sorted unique
// out: [8192, 4096] f32, zero except scattered columns.

#define BM 128
#define BN 128
#define BK 8
#define TM 8
#define TN 8
#define NTHREADS 256
#define KTOT 1024
#define NFULL 4096

__global__ __launch_bounds__(NTHREADS, 2)
void nsl_gemm_kernel(const float* __restrict__ x, const float* __restrict__ W,
                     const float* __restrict__ bias, const int* __restrict__ in_idx,
                     const int* __restrict__ out_idx, float* __restrict__ out) {
    __shared__ float As[2][BK][BM];
    __shared__ float Bs[2][BK][BN];
    __shared__ int   sIdx[KTOT];

    const int tid = threadIdx.x;
    const int m0 = blockIdx.y * BM;
    const int n0 = blockIdx.x * BN;

    // whole in_idx table in smem (4 KB), loaded once
    #pragma unroll
    for (int i = tid; i < KTOT; i += NTHREADS) sIdx[i] = in_idx[i];

    // A loader: thread -> (row m0+aRow, k = aK..aK+3), gathered columns of x
    // B loader: thread -> (row n0+bRow of W, k = bK..bK+3), contiguous -> float4
    const int aRow = tid >> 1;
    const int aK   = (tid & 1) * 4;
    const int bRow = tid >> 1;
    const int bK   = (tid & 1) * 4;

    const float* xrow = x + (size_t)(m0 + aRow) * NFULL;
    const float* wrow = W + (size_t)(n0 + bRow) * KTOT;

    __syncthreads();  // sIdx ready

    // ---- load tile 0 ----
    float  a_reg[4];
    float4 b_reg;
    #pragma unroll
    for (int i = 0; i < 4; i++) a_reg[i] = __ldg(xrow + sIdx[aK + i]);
    b_reg = *reinterpret_cast<const float4*>(wrow + bK);

    #pragma unroll
    for (int i = 0; i < 4; i++) As[0][aK + i][aRow] = a_reg[i];
    Bs[0][bK + 0][bRow] = b_reg.x;
    Bs[0][bK + 1][bRow] = b_reg.y;
    Bs[0][bK + 2][bRow] = b_reg.z;
    Bs[0][bK + 3][bRow] = b_reg.w;
    __syncthreads();

    const int ty = tid >> 4;   // 0..15 -> M sub-tile
    const int tx = tid & 15;   // 0..15 -> N sub-tile

    float acc[TM][TN];
    #pragma unroll
    for (int i = 0; i < TM; i++)
        #pragma unroll
        for (int j = 0; j < TN; j++) acc[i][j] = 0.f;

    const int numTiles = KTOT / BK;  // 128
    int buf = 0;
    for (int t = 0; t < numTiles; t++) {
        // prefetch next tile into registers (overlaps with compute below)
        if (t + 1 < numTiles) {
            const int k0 = (t + 1) * BK;
            #pragma unroll
            for (int i = 0; i < 4; i++) a_reg[i] = __ldg(xrow + sIdx[k0 + aK + i]);
            b_reg = *reinterpret_cast<const float4*>(wrow + k0 + bK);
        }
        // compute on current buffer
        #pragma unroll
        for (int k = 0; k < BK; k++) {
            float af[TM], bf[TN];
            #pragma unroll
            for (int i = 0; i < TM; i++) af[i] = As[buf][k][ty * TM + i];
            #pragma unroll
            for (int j = 0; j < TN; j++) bf[j] = Bs[buf][k][tx * TN + j];
            #pragma unroll
            for (int i = 0; i < TM; i++)
                #pragma unroll
                for (int j = 0; j < TN; j++)
                    acc[i][j] = fmaf(af[i], bf[j], acc[i][j]);
        }
        // stage prefetched tile into the other buffer
        if (t + 1 < numTiles) {
            const int nb = buf ^ 1;
            #pragma unroll
            for (int i = 0; i < 4; i++) As[nb][aK + i][aRow] = a_reg[i];
            Bs[nb][bK + 0][bRow] = b_reg.x;
            Bs[nb][bK + 1][bRow] = b_reg.y;
            Bs[nb][bK + 2][bRow] = b_reg.z;
            Bs[nb][bK + 3][bRow] = b_reg.w;
        }
        __syncthreads();
        buf ^= 1;
    }

    // ---- epilogue: bias + scatter into full-width output ----
    int   ocol[TN];
    float bv[TN];
    #pragma unroll
    for (int j = 0; j < TN; j++) {
        const int n = n0 + tx * TN + j;
        ocol[j] = __ldg(out_idx + n);
        bv[j]   = __ldg(bias + n);
    }
    #pragma unroll
    for (int i = 0; i < TM; i++) {
        float* orow = out + (size_t)(m0 + ty * TM + i) * NFULL;
        #pragma unroll
        for (int j = 0; j < TN; j++)
            orow[ocol[j]] = acc[i][j] + bv[j];
    }
}

extern "C" void kernel_launch(void* const* d_in, const int* in_sizes, int n_in,
                              void* d_out, int out_size) {
    const float* x       = (const float*)d_in[0];
    const float* W       = (const float*)d_in[1];
    const float* b       = (const float*)d_in[2];
    const int*   in_idx  = (const int*)d_in[3];
    const int*   out_idx = (const int*)d_in[4];
    float*       out     = (float*)d_out;

    const int M = in_sizes[0] / NFULL;  // 8192

    // zero-fill the full output (inactive columns must be 0; d_out is poisoned)
    cudaMemsetAsync(out, 0, (size_t)out_size * sizeof(float), 0);

    dim3 grid(KTOT / BN, M / BM);  // (8, 64) = 512 CTAs
    nsl_gemm_kernel<<<grid, NTHREADS>>>(x, W, b, in_idx, out_idx, out);
}

// round 4
// speedup vs baseline: 1.8199x; 1.8199x over previous
#include <cuda_runtime.h>
#include <cuda_bf16.h>
#include <cstdint>

// ---------------- problem constants ----------------
#define MROWS   8192
#define NFULL   4096
#define KACT    1024
#define NACT    1024

#define BM      128
#define BN      128
#define BKB     32                    // bf16 k-elements per stage chunk
#define NITER   (KACT / BKB)          // 32
#define STAGES  3
#define RSTB    40                    // bf16 row stride (80 bytes, 16B-aligned rows)
#define PLANE_BYTES (128 * RSTB * 2)  // 10240
#define STAGE_BYTES (4 * PLANE_BYTES) // A_hi, A_lo, B_hi, B_lo
#define SMEM_BYTES  (STAGES * STAGE_BYTES)  // 122880

// scratch planes: split-bf16 activations (gathered) and weights
__device__ __nv_bfloat16 g_xh[(size_t)MROWS * KACT];
__device__ __nv_bfloat16 g_xl[(size_t)MROWS * KACT];
__device__ __nv_bfloat16 g_wh[(size_t)NACT * KACT];
__device__ __nv_bfloat16 g_wl[(size_t)NACT * KACT];
__device__ int g_pos[NFULL];

// ---------------- helpers ----------------
__device__ __forceinline__ uint32_t smem_u32(const void* p) {
    uint32_t a;
    asm("{ .reg .u64 t; cvta.to.shared.u64 t, %1; cvt.u32.u64 %0, t; }" : "=r"(a) : "l"(p));
    return a;
}
__device__ __forceinline__ void cp_async16(uint32_t dst, const void* src) {
    asm volatile("cp.async.cg.shared.global [%0], [%1], 16;" :: "r"(dst), "l"(src));
}
__device__ __forceinline__ void ldsm4(uint32_t* r, uint32_t addr) {
    asm volatile("ldmatrix.sync.aligned.m8n8.x4.shared.b16 {%0,%1,%2,%3}, [%4];"
                 : "=r"(r[0]), "=r"(r[1]), "=r"(r[2]), "=r"(r[3]) : "r"(addr));
}
__device__ __forceinline__ void mma_bf16(float* d, const uint32_t* a,
                                         uint32_t b0, uint32_t b1) {
    asm volatile(
        "mma.sync.aligned.m16n8k16.row.col.f32.bf16.bf16.f32 "
        "{%0,%1,%2,%3}, {%4,%5,%6,%7}, {%8,%9}, {%0,%1,%2,%3};"
        : "+f"(d[0]), "+f"(d[1]), "+f"(d[2]), "+f"(d[3])
        : "r"(a[0]), "r"(a[1]), "r"(a[2]), "r"(a[3]), "r"(b0), "r"(b1));
}
__device__ __forceinline__ uint32_t pack_bf2(float a, float b) {
    __nv_bfloat162 t = __floats2bfloat162_rn(a, b);   // .x = a (low), .y = b (high)
    return *reinterpret_cast<uint32_t*>(&t);
}

// ---------------- kernel 1: inverse column map ----------------
__global__ void build_pos_kernel(const int* __restrict__ in_idx) {
    int c = blockIdx.x * blockDim.x + threadIdx.x;
    if (c >= NFULL) return;
    int lo = 0, hi = KACT - 1, found = -1;
    while (lo <= hi) {
        int mid = (lo + hi) >> 1;
        int v = __ldg(in_idx + mid);
        if (v == c) { found = mid; break; }
        if (v < c) lo = mid + 1; else hi = mid - 1;
    }
    g_pos[c] = found;
}

// ---------------- kernel 2: gather + bf16 split of x ----------------
__global__ __launch_bounds__(256) void gather_split_kernel(const float* __restrict__ x) {
    __shared__ int s_pos[NFULL];
    const int tid = threadIdx.x;
    for (int i = tid; i < NFULL; i += 256) s_pos[i] = g_pos[i];
    __syncthreads();

    const size_t r0 = (size_t)blockIdx.x * 4;
    const float4* __restrict__ x4 = (const float4*)x;
    #pragma unroll
    for (int i = 0; i < 16; i++) {
        int f = tid + i * 256;
        size_t row = r0 + (f >> 10);
        int c4 = f & 1023;
        float4 v = x4[row * (NFULL / 4) + c4];
        int c = c4 * 4;
        float vv[4] = {v.x, v.y, v.z, v.w};
        __nv_bfloat16* dh = g_xh + row * KACT;
        __nv_bfloat16* dl = g_xl + row * KACT;
        #pragma unroll
        for (int j = 0; j < 4; j++) {
            int p = s_pos[c + j];
            if (p >= 0) {
                __nv_bfloat16 h = __float2bfloat16_rn(vv[j]);
                dh[p] = h;
                dl[p] = __float2bfloat16_rn(vv[j] - __bfloat162float(h));
            }
        }
    }
}

// ---------------- kernel 3: bf16 split of W (packed u32 stores) ----------------
__global__ __launch_bounds__(256) void split_w_kernel(const float* __restrict__ W) {
    int i = blockIdx.x * blockDim.x + threadIdx.x;      // float4 index
    float4 v = ((const float4*)W)[i];
    float h0 = __bfloat162float(__float2bfloat16_rn(v.x));
    float h1 = __bfloat162float(__float2bfloat16_rn(v.y));
    float h2 = __bfloat162float(__float2bfloat16_rn(v.z));
    float h3 = __bfloat162float(__float2bfloat16_rn(v.w));
    uint2 hp, lp;
    hp.x = pack_bf2(h0, h1);           hp.y = pack_bf2(h2, h3);
    lp.x = pack_bf2(v.x - h0, v.y - h1); lp.y = pack_bf2(v.z - h2, v.w - h3);
    ((uint2*)g_wh)[i] = hp;
    ((uint2*)g_wl)[i] = lp;
}

// ---------------- kernel 4: bf16x3 mma GEMM + bias + scatter ----------------
extern __shared__ char dynsmem[];

__global__ __launch_bounds__(256, 1)
void nsl_mma_gemm(const float* __restrict__ bias, const int* __restrict__ out_idx,
                  float* __restrict__ out) {
    __shared__ float s_bias[BN];
    __shared__ int   s_oidx[BN];

    const int tid  = threadIdx.x;
    const int wid  = tid >> 5;
    const int lane = tid & 31;
    const int wm   = wid >> 1;        // 0..3
    const int wn   = wid & 1;         // 0..1
    const int m0   = blockIdx.y * BM;
    const int n0   = blockIdx.x * BN;

    if (tid < BN) {
        s_oidx[tid] = __ldg(out_idx + n0 + tid);
        s_bias[tid] = __ldg(bias + n0 + tid);
    }

    const uint32_t sbase = smem_u32(dynsmem);
    const __nv_bfloat16* __restrict__ gAh = g_xh + (size_t)m0 * KACT;
    const __nv_bfloat16* __restrict__ gAl = g_xl + (size_t)m0 * KACT;
    const __nv_bfloat16* __restrict__ gBh = g_wh + (size_t)n0 * KACT;
    const __nv_bfloat16* __restrict__ gBl = g_wl + (size_t)n0 * KACT;

    // one plane = 128 rows x 32 bf16 (64B) -> 512 x 16B segs, 2 per thread
    auto load_plane = [&](uint32_t dst, const __nv_bfloat16* src, int kc) {
        #pragma unroll
        for (int i = 0; i < 2; i++) {
            int s = tid + i * 256;
            int r = s >> 2, p = s & 3;
            cp_async16(dst + (uint32_t)(r * 80 + p * 16),
                       src + (size_t)r * KACT + kc * BKB + p * 8);
        }
    };
    auto load_stage = [&](int stage, int kc) {
        const uint32_t sb = sbase + stage * STAGE_BYTES;
        load_plane(sb,                   gAh, kc);
        load_plane(sb + PLANE_BYTES,     gAl, kc);
        load_plane(sb + 2 * PLANE_BYTES, gBh, kc);
        load_plane(sb + 3 * PLANE_BYTES, gBl, kc);
        asm volatile("cp.async.commit_group;");
    };

    // ldmatrix per-lane offsets (bytes within a plane)
    const int lrow = lane & 15;
    const uint32_t khalf = (uint32_t)(lane >> 4) * 16;
    uint32_t aOff[2], bOff[4];
    #pragma unroll
    for (int f = 0; f < 2; f++)
        aOff[f] = (uint32_t)((wm * 32 + f * 16 + lrow) * 80) + khalf;
    #pragma unroll
    for (int p = 0; p < 4; p++)
        bOff[p] = (uint32_t)((wn * 64 + p * 16 + lrow) * 80) + khalf;

    float acc[2][8][4];
    #pragma unroll
    for (int i = 0; i < 2; i++)
        #pragma unroll
        for (int j = 0; j < 8; j++)
            #pragma unroll
            for (int q = 0; q < 4; q++) acc[i][j][q] = 0.f;

    load_stage(0, 0);
    load_stage(1, 1);

    for (int t = 0; t < NITER; t++) {
        // TAIL FIX: last iteration must drain ALL outstanding groups
        if (t < NITER - 1) asm volatile("cp.async.wait_group 1;" ::: "memory");
        else               asm volatile("cp.async.wait_group 0;" ::: "memory");
        __syncthreads();

        const uint32_t sb = sbase + (t % STAGES) * STAGE_BYTES;
        #pragma unroll
        for (int kk = 0; kk < 2; kk++) {            // 2 x k16 steps
            const uint32_t ko = kk * 32;            // 16 bf16 = 32B
            uint32_t ah[2][4], al[2][4], bh[4][4], bl[4][4];
            ldsm4(ah[0], sb + ko + aOff[0]);
            ldsm4(ah[1], sb + ko + aOff[1]);
            ldsm4(al[0], sb + PLANE_BYTES + ko + aOff[0]);
            ldsm4(al[1], sb + PLANE_BYTES + ko + aOff[1]);
            #pragma unroll
            for (int p = 0; p < 4; p++) ldsm4(bh[p], sb + 2 * PLANE_BYTES + ko + bOff[p]);
            #pragma unroll
            for (int p = 0; p < 4; p++) ldsm4(bl[p], sb + 3 * PLANE_BYTES + ko + bOff[p]);

            #pragma unroll
            for (int mi = 0; mi < 2; mi++)
                #pragma unroll
                for (int p = 0; p < 4; p++) {
                    // hi*hi
                    mma_bf16(acc[mi][2 * p + 0], ah[mi], bh[p][0], bh[p][2]);
                    mma_bf16(acc[mi][2 * p + 1], ah[mi], bh[p][1], bh[p][3]);
                    // hi*lo
                    mma_bf16(acc[mi][2 * p + 0], ah[mi], bl[p][0], bl[p][2]);
                    mma_bf16(acc[mi][2 * p + 1], ah[mi], bl[p][1], bl[p][3]);
                    // lo*hi
                    mma_bf16(acc[mi][2 * p + 0], al[mi], bh[p][0], bh[p][2]);
                    mma_bf16(acc[mi][2 * p + 1], al[mi], bh[p][1], bh[p][3]);
                }
        }
        __syncthreads();
        if (t + STAGES - 1 < NITER) load_stage((t + STAGES - 1) % STAGES, t + STAGES - 1);
    }

    // ---- epilogue: bias + scatter ----
    const int rq = lane >> 2, cq = (lane & 3) * 2;
    #pragma unroll
    for (int mi = 0; mi < 2; mi++) {
        const int rbase = m0 + wm * 32 + mi * 16 + rq;
        float* __restrict__ row0 = out + (size_t)rbase * NFULL;
        float* __restrict__ row1 = row0 + (size_t)8 * NFULL;
        #pragma unroll
        for (int nf = 0; nf < 8; nf++) {
            const int nl = wn * 64 + nf * 8 + cq;
            const float* c = acc[mi][nf];
            row0[s_oidx[nl]]     = c[0] + s_bias[nl];
            row0[s_oidx[nl + 1]] = c[1] + s_bias[nl + 1];
            row1[s_oidx[nl]]     = c[2] + s_bias[nl];
            row1[s_oidx[nl + 1]] = c[3] + s_bias[nl + 1];
        }
    }
}

// ---------------- launch ----------------
extern "C" void kernel_launch(void* const* d_in, const int* in_sizes, int n_in,
                              void* d_out, int out_size) {
    const float* x       = (const float*)d_in[0];
    const float* W       = (const float*)d_in[1];
    const float* b       = (const float*)d_in[2];
    const int*   in_idx  = (const int*)d_in[3];
    const int*   out_idx = (const int*)d_in[4];
    float*       out     = (float*)d_out;

    static bool attr_set = false;
    if (!attr_set) {
        cudaFuncSetAttribute(nsl_mma_gemm, cudaFuncAttributeMaxDynamicSharedMemorySize,
                             SMEM_BYTES);
        attr_set = true;
    }

    cudaMemsetAsync(out, 0, (size_t)out_size * sizeof(float), 0);

    build_pos_kernel<<<(NFULL + 255) / 256, 256>>>(in_idx);
    gather_split_kernel<<<MROWS / 4, 256>>>(x);
    split_w_kernel<<<(NACT * KACT / 4) / 256, 256>>>(W);

    dim3 grid(NACT / BN, MROWS / BM);   // (8, 64) = 512 CTAs
    nsl_mma_gemm<<<grid, 256, SMEM_BYTES>>>(b, out_idx, out);
}

// round 5
// speedup vs baseline: 1.9277x; 1.0592x over previous
#include <cuda_runtime.h>
#include <cuda_bf16.h>
#include <cstdint>

// ---------------- problem constants ----------------
#define MROWS   8192
#define NFULL   4096
#define KACT    1024
#define NACT    1024

#define BM      128
#define BN      128
#define BKB     32                    // bf16 k-elements per stage chunk
#define NITER   (KACT / BKB)          // 32
#define STAGES  4
#define PLANE_BYTES (128 * 80)        // 128 rows x 40 bf16 (80B, 64B data + pad)
#define STAGE_BYTES (4 * PLANE_BYTES) // A_hi, A_lo, B_hi, B_lo = 40960
#define SMEM_BYTES  (STAGES * STAGE_BYTES)  // 163840
#define NTHREADS 512

// scratch planes: split-bf16 activations (gathered) and weights
__device__ __nv_bfloat16 g_xh[(size_t)MROWS * KACT];
__device__ __nv_bfloat16 g_xl[(size_t)MROWS * KACT];
__device__ __nv_bfloat16 g_wh[(size_t)NACT * KACT];
__device__ __nv_bfloat16 g_wl[(size_t)NACT * KACT];
__device__ int g_pos[NFULL];

// ---------------- helpers ----------------
__device__ __forceinline__ uint32_t smem_u32(const void* p) {
    uint32_t a;
    asm("{ .reg .u64 t; cvta.to.shared.u64 t, %1; cvt.u32.u64 %0, t; }" : "=r"(a) : "l"(p));
    return a;
}
__device__ __forceinline__ void cp_async16(uint32_t dst, const void* src) {
    asm volatile("cp.async.cg.shared.global [%0], [%1], 16;" :: "r"(dst), "l"(src));
}
__device__ __forceinline__ void ldsm4(uint32_t* r, uint32_t addr) {
    asm volatile("ldmatrix.sync.aligned.m8n8.x4.shared.b16 {%0,%1,%2,%3}, [%4];"
                 : "=r"(r[0]), "=r"(r[1]), "=r"(r[2]), "=r"(r[3]) : "r"(addr));
}
__device__ __forceinline__ void mma_bf16(float* d, const uint32_t* a,
                                         uint32_t b0, uint32_t b1) {
    asm volatile(
        "mma.sync.aligned.m16n8k16.row.col.f32.bf16.bf16.f32 "
        "{%0,%1,%2,%3}, {%4,%5,%6,%7}, {%8,%9}, {%0,%1,%2,%3};"
        : "+f"(d[0]), "+f"(d[1]), "+f"(d[2]), "+f"(d[3])
        : "r"(a[0]), "r"(a[1]), "r"(a[2]), "r"(a[3]), "r"(b0), "r"(b1));
}
__device__ __forceinline__ uint32_t pack_bf2(float a, float b) {
    __nv_bfloat162 t = __floats2bfloat162_rn(a, b);
    return *reinterpret_cast<uint32_t*>(&t);
}

// ---------------- kernel 1: inverse column map ----------------
__global__ void build_pos_kernel(const int* __restrict__ in_idx) {
    int c = blockIdx.x * blockDim.x + threadIdx.x;
    if (c >= NFULL) return;
    int lo = 0, hi = KACT - 1, found = -1;
    while (lo <= hi) {
        int mid = (lo + hi) >> 1;
        int v = __ldg(in_idx + mid);
        if (v == c) { found = mid; break; }
        if (v < c) lo = mid + 1; else hi = mid - 1;
    }
    g_pos[c] = found;
}

// ---------------- kernel 2: gather + bf16 split of x ----------------
__global__ __launch_bounds__(256) void gather_split_kernel(const float* __restrict__ x) {
    __shared__ int s_pos[NFULL];
    const int tid = threadIdx.x;
    for (int i = tid; i < NFULL; i += 256) s_pos[i] = g_pos[i];
    __syncthreads();

    const size_t r0 = (size_t)blockIdx.x * 4;
    const float4* __restrict__ x4 = (const float4*)x;
    #pragma unroll
    for (int i = 0; i < 16; i++) {
        int f = tid + i * 256;
        size_t row = r0 + (f >> 10);
        int c4 = f & 1023;
        float4 v = x4[row * (NFULL / 4) + c4];
        int c = c4 * 4;
        float vv[4] = {v.x, v.y, v.z, v.w};
        __nv_bfloat16* dh = g_xh + row * KACT;
        __nv_bfloat16* dl = g_xl + row * KACT;
        #pragma unroll
        for (int j = 0; j < 4; j++) {
            int p = s_pos[c + j];
            if (p >= 0) {
                __nv_bfloat16 h = __float2bfloat16_rn(vv[j]);
                dh[p] = h;
                dl[p] = __float2bfloat16_rn(vv[j] - __bfloat162float(h));
            }
        }
    }
}

// ---------------- kernel 3: bf16 split of W ----------------
__global__ __launch_bounds__(256) void split_w_kernel(const float* __restrict__ W) {
    int i = blockIdx.x * blockDim.x + threadIdx.x;
    float4 v = ((const float4*)W)[i];
    float h0 = __bfloat162float(__float2bfloat16_rn(v.x));
    float h1 = __bfloat162float(__float2bfloat16_rn(v.y));
    float h2 = __bfloat162float(__float2bfloat16_rn(v.z));
    float h3 = __bfloat162float(__float2bfloat16_rn(v.w));
    uint2 hp, lp;
    hp.x = pack_bf2(h0, h1);             hp.y = pack_bf2(h2, h3);
    lp.x = pack_bf2(v.x - h0, v.y - h1); lp.y = pack_bf2(v.z - h2, v.w - h3);
    ((uint2*)g_wh)[i] = hp;
    ((uint2*)g_wl)[i] = lp;
}

// ---------------- kernel 4: bf16x3 mma GEMM + bias + scatter ----------------
extern __shared__ char dynsmem[];

__global__ __launch_bounds__(NTHREADS, 1)
void nsl_mma_gemm(const float* __restrict__ bias, const int* __restrict__ out_idx,
                  float* __restrict__ out) {
    __shared__ float s_bias[BN];
    __shared__ int   s_oidx[BN];

    const int tid  = threadIdx.x;
    const int wid  = tid >> 5;
    const int lane = tid & 31;
    const int wm   = wid >> 2;        // 0..3 : 32-row band
    const int wn   = wid & 3;         // 0..3 : 32-col band
    const int m0   = blockIdx.y * BM;
    const int n0   = blockIdx.x * BN;

    if (tid < BN) {
        s_oidx[tid] = __ldg(out_idx + n0 + tid);
        s_bias[tid] = __ldg(bias + n0 + tid);
    }

    const uint32_t sbase = smem_u32(dynsmem);
    const __nv_bfloat16* __restrict__ gAh = g_xh + (size_t)m0 * KACT;
    const __nv_bfloat16* __restrict__ gAl = g_xl + (size_t)m0 * KACT;
    const __nv_bfloat16* __restrict__ gBh = g_wh + (size_t)n0 * KACT;
    const __nv_bfloat16* __restrict__ gBl = g_wl + (size_t)n0 * KACT;

    // one plane = 128 rows x 32 bf16 (64B) = 512 x 16B segs -> 1 per thread
    auto load_plane = [&](uint32_t dst, const __nv_bfloat16* src, int kc) {
        int r = tid >> 2, p = tid & 3;
        cp_async16(dst + (uint32_t)(r * 80 + p * 16),
                   src + (size_t)r * KACT + kc * BKB + p * 8);
    };
    auto load_stage = [&](int stage, int kc) {
        const uint32_t sb = sbase + stage * STAGE_BYTES;
        load_plane(sb,                   gAh, kc);
        load_plane(sb + PLANE_BYTES,     gAl, kc);
        load_plane(sb + 2 * PLANE_BYTES, gBh, kc);
        load_plane(sb + 3 * PLANE_BYTES, gBl, kc);
        asm volatile("cp.async.commit_group;");
    };

    // ldmatrix per-lane offsets (bytes within a plane)
    const int lrow = lane & 15;
    const uint32_t khalf = (uint32_t)(lane >> 4) * 16;
    uint32_t aOff[2], bOff[2];
    #pragma unroll
    for (int f = 0; f < 2; f++)
        aOff[f] = (uint32_t)((wm * 32 + f * 16 + lrow) * 80) + khalf;
    #pragma unroll
    for (int p = 0; p < 2; p++)
        bOff[p] = (uint32_t)((wn * 32 + p * 16 + lrow) * 80) + khalf;

    float acc[2][4][4];
    #pragma unroll
    for (int i = 0; i < 2; i++)
        #pragma unroll
        for (int j = 0; j < 4; j++)
            #pragma unroll
            for (int q = 0; q < 4; q++) acc[i][j][q] = 0.f;

    load_stage(0, 0);
    load_stage(1, 1);
    load_stage(2, 2);

    for (int t = 0; t < NITER; t++) {
        if      (t < NITER - 2) asm volatile("cp.async.wait_group 2;" ::: "memory");
        else if (t < NITER - 1) asm volatile("cp.async.wait_group 1;" ::: "memory");
        else                    asm volatile("cp.async.wait_group 0;" ::: "memory");
        __syncthreads();
        // slot being overwritten = (t+3)%4 = (t-1)%4, fully consumed before the
        // barrier above -> safe to issue loads before this iteration's compute
        if (t + STAGES - 1 < NITER)
            load_stage((t + STAGES - 1) % STAGES, t + STAGES - 1);

        const uint32_t sb = sbase + (t % STAGES) * STAGE_BYTES;
        #pragma unroll
        for (int kk = 0; kk < 2; kk++) {            // 2 x k16 steps
            const uint32_t ko = kk * 32;            // 16 bf16 = 32B
            uint32_t ah[2][4], al[2][4], bh[2][4], bl[2][4];
            ldsm4(ah[0], sb + ko + aOff[0]);
            ldsm4(ah[1], sb + ko + aOff[1]);
            ldsm4(al[0], sb + PLANE_BYTES + ko + aOff[0]);
            ldsm4(al[1], sb + PLANE_BYTES + ko + aOff[1]);
            ldsm4(bh[0], sb + 2 * PLANE_BYTES + ko + bOff[0]);
            ldsm4(bh[1], sb + 2 * PLANE_BYTES + ko + bOff[1]);
            ldsm4(bl[0], sb + 3 * PLANE_BYTES + ko + bOff[0]);
            ldsm4(bl[1], sb + 3 * PLANE_BYTES + ko + bOff[1]);

            // term-major: max dependency distance on each accumulator
            #pragma unroll
            for (int mi = 0; mi < 2; mi++)
                #pragma unroll
                for (int p = 0; p < 2; p++) {
                    mma_bf16(acc[mi][2 * p + 0], ah[mi], bh[p][0], bh[p][2]);
                    mma_bf16(acc[mi][2 * p + 1], ah[mi], bh[p][1], bh[p][3]);
                }
            #pragma unroll
            for (int mi = 0; mi < 2; mi++)
                #pragma unroll
                for (int p = 0; p < 2; p++) {
                    mma_bf16(acc[mi][2 * p + 0], ah[mi], bl[p][0], bl[p][2]);
                    mma_bf16(acc[mi][2 * p + 1], ah[mi], bl[p][1], bl[p][3]);
                }
            #pragma unroll
            for (int mi = 0; mi < 2; mi++)
                #pragma unroll
                for (int p = 0; p < 2; p++) {
                    mma_bf16(acc[mi][2 * p + 0], al[mi], bh[p][0], bh[p][2]);
                    mma_bf16(acc[mi][2 * p + 1], al[mi], bh[p][1], bh[p][3]);
                }
        }
    }

    // ---- epilogue: bias + scatter ----
    const int rq = lane >> 2, cq = (lane & 3) * 2;
    #pragma unroll
    for (int mi = 0; mi < 2; mi++) {
        const int rbase = m0 + wm * 32 + mi * 16 + rq;
        float* __restrict__ row0 = out + (size_t)rbase * NFULL;
        float* __restrict__ row1 = row0 + (size_t)8 * NFULL;
        #pragma unroll
        for (int nf = 0; nf < 4; nf++) {
            const int nl = wn * 32 + nf * 8 + cq;
            const float* c = acc[mi][nf];
            row0[s_oidx[nl]]     = c[0] + s_bias[nl];
            row0[s_oidx[nl + 1]] = c[1] + s_bias[nl + 1];
            row1[s_oidx[nl]]     = c[2] + s_bias[nl];
            row1[s_oidx[nl + 1]] = c[3] + s_bias[nl + 1];
        }
    }
}

// ---------------- launch ----------------
extern "C" void kernel_launch(void* const* d_in, const int* in_sizes, int n_in,
                              void* d_out, int out_size) {
    const float* x       = (const float*)d_in[0];
    const float* W       = (const float*)d_in[1];
    const float* b       = (const float*)d_in[2];
    const int*   in_idx  = (const int*)d_in[3];
    const int*   out_idx = (const int*)d_in[4];
    float*       out     = (float*)d_out;

    static bool attr_set = false;
    if (!attr_set) {
        cudaFuncSetAttribute(nsl_mma_gemm, cudaFuncAttributeMaxDynamicSharedMemorySize,
                             SMEM_BYTES);
        attr_set = true;
    }

    cudaMemsetAsync(out, 0, (size_t)out_size * sizeof(float), 0);

    build_pos_kernel<<<(NFULL + 255) / 256, 256>>>(in_idx);
    gather_split_kernel<<<MROWS / 4, 256>>>(x);
    split_w_kernel<<<(NACT * KACT / 4) / 256, 256>>>(W);

    dim3 grid(NACT / BN, MROWS / BM);   // (8, 64) = 512 CTAs
    nsl_mma_gemm<<<grid, NTHREADS, SMEM_BYTES>>>(b, out_idx, out);
}

// round 6
// speedup vs baseline: 2.1022x; 1.0905x over previous
#include <cuda_runtime.h>
#include <cuda_bf16.h>
#include <cstdint>

// ---------------- problem constants ----------------
#define MROWS   8192
#define NFULL   4096
#define KACT    1024
#define NACT    1024

#define BM      128
#define BN      64
#define BKB     32                        // bf16 k-elements per stage chunk
#define NITER   (KACT / BKB)              // 32
#define STAGES  3
#define A_PLANE (128 * 80)                // 10240 B
#define B_PLANE (64 * 80)                 // 5120 B
#define STAGE_BYTES (2 * A_PLANE + 2 * B_PLANE)   // 30720
#define SMEM_BYTES  (STAGES * STAGE_BYTES)        // 92160
#define NTHREADS 256

// scratch planes: split-bf16 activations (gathered) and weights
__device__ __nv_bfloat16 g_xh[(size_t)MROWS * KACT];
__device__ __nv_bfloat16 g_xl[(size_t)MROWS * KACT];
__device__ __nv_bfloat16 g_wh[(size_t)NACT * KACT];
__device__ __nv_bfloat16 g_wl[(size_t)NACT * KACT];
__device__ int g_pos[NFULL];

// ---------------- helpers ----------------
__device__ __forceinline__ uint32_t smem_u32(const void* p) {
    uint32_t a;
    asm("{ .reg .u64 t; cvta.to.shared.u64 t, %1; cvt.u32.u64 %0, t; }" : "=r"(a) : "l"(p));
    return a;
}
__device__ __forceinline__ void cp_async16(uint32_t dst, const void* src) {
    asm volatile("cp.async.cg.shared.global [%0], [%1], 16;" :: "r"(dst), "l"(src));
}
__device__ __forceinline__ void ldsm4(uint32_t* r, uint32_t addr) {
    asm volatile("ldmatrix.sync.aligned.m8n8.x4.shared.b16 {%0,%1,%2,%3}, [%4];"
                 : "=r"(r[0]), "=r"(r[1]), "=r"(r[2]), "=r"(r[3]) : "r"(addr));
}
__device__ __forceinline__ void mma_bf16(float* d, const uint32_t* a,
                                         uint32_t b0, uint32_t b1) {
    asm volatile(
        "mma.sync.aligned.m16n8k16.row.col.f32.bf16.bf16.f32 "
        "{%0,%1,%2,%3}, {%4,%5,%6,%7}, {%8,%9}, {%0,%1,%2,%3};"
        : "+f"(d[0]), "+f"(d[1]), "+f"(d[2]), "+f"(d[3])
        : "r"(a[0]), "r"(a[1]), "r"(a[2]), "r"(a[3]), "r"(b0), "r"(b1));
}
__device__ __forceinline__ uint32_t pack_bf2(float a, float b) {
    __nv_bfloat162 t = __floats2bfloat162_rn(a, b);
    return *reinterpret_cast<uint32_t*>(&t);
}

// ---------------- kernel 1: inverse column map ----------------
__global__ void build_pos_kernel(const int* __restrict__ in_idx) {
    int c = blockIdx.x * blockDim.x + threadIdx.x;
    if (c >= NFULL) return;
    int lo = 0, hi = KACT - 1, found = -1;
    while (lo <= hi) {
        int mid = (lo + hi) >> 1;
        int v = __ldg(in_idx + mid);
        if (v == c) { found = mid; break; }
        if (v < c) lo = mid + 1; else hi = mid - 1;
    }
    g_pos[c] = found;
}

// ---------------- kernel 2: gather + bf16 split of x ----------------
__global__ __launch_bounds__(256) void gather_split_kernel(const float* __restrict__ x) {
    __shared__ int s_pos[NFULL];
    const int tid = threadIdx.x;
    for (int i = tid; i < NFULL; i += 256) s_pos[i] = g_pos[i];
    __syncthreads();

    const size_t r0 = (size_t)blockIdx.x * 4;
    const float4* __restrict__ x4 = (const float4*)x;
    #pragma unroll
    for (int i = 0; i < 16; i++) {
        int f = tid + i * 256;
        size_t row = r0 + (f >> 10);
        int c4 = f & 1023;
        float4 v = x4[row * (NFULL / 4) + c4];
        int c = c4 * 4;
        float vv[4] = {v.x, v.y, v.z, v.w};
        __nv_bfloat16* dh = g_xh + row * KACT;
        __nv_bfloat16* dl = g_xl + row * KACT;
        #pragma unroll
        for (int j = 0; j < 4; j++) {
            int p = s_pos[c + j];
            if (p >= 0) {
                __nv_bfloat16 h = __float2bfloat16_rn(vv[j]);
                dh[p] = h;
                dl[p] = __float2bfloat16_rn(vv[j] - __bfloat162float(h));
            }
        }
    }
}

// ---------------- kernel 3: bf16 split of W ----------------
__global__ __launch_bounds__(256) void split_w_kernel(const float* __restrict__ W) {
    int i = blockIdx.x * blockDim.x + threadIdx.x;
    float4 v = ((const float4*)W)[i];
    float h0 = __bfloat162float(__float2bfloat16_rn(v.x));
    float h1 = __bfloat162float(__float2bfloat16_rn(v.y));
    float h2 = __bfloat162float(__float2bfloat16_rn(v.z));
    float h3 = __bfloat162float(__float2bfloat16_rn(v.w));
    uint2 hp, lp;
    hp.x = pack_bf2(h0, h1);             hp.y = pack_bf2(h2, h3);
    lp.x = pack_bf2(v.x - h0, v.y - h1); lp.y = pack_bf2(v.z - h2, v.w - h3);
    ((uint2*)g_wh)[i] = hp;
    ((uint2*)g_wl)[i] = lp;
}

// ---------------- kernel 4: bf16x3 mma GEMM + bias + scatter ----------------
extern __shared__ char dynsmem[];

__global__ __launch_bounds__(NTHREADS, 2)
void nsl_mma_gemm(const float* __restrict__ bias, const int* __restrict__ out_idx,
                  float* __restrict__ out) {
    __shared__ float s_bias[BN];
    __shared__ int   s_oidx[BN];

    const int tid  = threadIdx.x;
    const int wid  = tid >> 5;
    const int lane = tid & 31;
    const int wm   = wid >> 1;        // 0..3 : 32-row band
    const int wn   = wid & 1;         // 0..1 : 32-col band
    const int m0   = blockIdx.y * BM;
    const int n0   = blockIdx.x * BN;

    if (tid < BN) {
        s_oidx[tid] = __ldg(out_idx + n0 + tid);
        s_bias[tid] = __ldg(bias + n0 + tid);
    }

    const uint32_t sbase = smem_u32(dynsmem);
    const __nv_bfloat16* __restrict__ gAh = g_xh + (size_t)m0 * KACT;
    const __nv_bfloat16* __restrict__ gAl = g_xl + (size_t)m0 * KACT;
    const __nv_bfloat16* __restrict__ gBh = g_wh + (size_t)n0 * KACT;
    const __nv_bfloat16* __restrict__ gBl = g_wl + (size_t)n0 * KACT;

    // A plane: 128 rows x 4 segs = 512 segs -> 2/thread
    auto load_planeA = [&](uint32_t dst, const __nv_bfloat16* src, int kc) {
        #pragma unroll
        for (int i = 0; i < 2; i++) {
            int s = tid + i * 256;
            int r = s >> 2, p = s & 3;
            cp_async16(dst + (uint32_t)(r * 80 + p * 16),
                       src + (size_t)r * KACT + kc * BKB + p * 8);
        }
    };
    // B plane: 64 rows x 4 segs = 256 segs -> 1/thread
    auto load_planeB = [&](uint32_t dst, const __nv_bfloat16* src, int kc) {
        int r = tid >> 2, p = tid & 3;
        cp_async16(dst + (uint32_t)(r * 80 + p * 16),
                   src + (size_t)r * KACT + kc * BKB + p * 8);
    };
    auto load_stage = [&](int stage, int kc) {
        const uint32_t sb = sbase + stage * STAGE_BYTES;
        load_planeA(sb,               gAh, kc);
        load_planeA(sb + A_PLANE,     gAl, kc);
        load_planeB(sb + 2 * A_PLANE,           gBh, kc);
        load_planeB(sb + 2 * A_PLANE + B_PLANE, gBl, kc);
        asm volatile("cp.async.commit_group;");
    };

    // ldmatrix per-lane offsets (bytes within a plane)
    const int lrow = lane & 15;
    const uint32_t khalf = (uint32_t)(lane >> 4) * 16;
    uint32_t aOff[2], bOff[2];
    #pragma unroll
    for (int f = 0; f < 2; f++)
        aOff[f] = (uint32_t)((wm * 32 + f * 16 + lrow) * 80) + khalf;
    #pragma unroll
    for (int p = 0; p < 2; p++)
        bOff[p] = (uint32_t)(2 * A_PLANE + (wn * 32 + p * 16 + lrow) * 80) + khalf;

    float acc[2][4][4];
    #pragma unroll
    for (int i = 0; i < 2; i++)
        #pragma unroll
        for (int j = 0; j < 4; j++)
            #pragma unroll
            for (int q = 0; q < 4; q++) acc[i][j][q] = 0.f;

    load_stage(0, 0);
    load_stage(1, 1);

    for (int t = 0; t < NITER; t++) {
        if (t < NITER - 1) asm volatile("cp.async.wait_group 1;" ::: "memory");
        else               asm volatile("cp.async.wait_group 0;" ::: "memory");
        __syncthreads();
        // slot (t+2)%3 == (t-1)%3 was consumed last iteration -> safe to refill now
        if (t + 2 < NITER) load_stage((t + 2) % STAGES, t + 2);

        const uint32_t sb = sbase + (t % STAGES) * STAGE_BYTES;
        #pragma unroll
        for (int kk = 0; kk < 2; kk++) {            // 2 x k16 steps
            const uint32_t ko = kk * 32;            // 16 bf16 = 32B
            uint32_t ah[2][4], al[2][4], bh[2][4], bl[2][4];
            ldsm4(ah[0], sb + ko + aOff[0]);
            ldsm4(ah[1], sb + ko + aOff[1]);
            ldsm4(al[0], sb + A_PLANE + ko + aOff[0]);
            ldsm4(al[1], sb + A_PLANE + ko + aOff[1]);
            ldsm4(bh[0], sb + ko + bOff[0]);
            ldsm4(bh[1], sb + ko + bOff[1]);
            ldsm4(bl[0], sb + B_PLANE + ko + bOff[0]);
            ldsm4(bl[1], sb + B_PLANE + ko + bOff[1]);

            // term-major: max dependency distance on each accumulator
            #pragma unroll
            for (int mi = 0; mi < 2; mi++)
                #pragma unroll
                for (int p = 0; p < 2; p++) {
                    mma_bf16(acc[mi][2 * p + 0], ah[mi], bh[p][0], bh[p][2]);
                    mma_bf16(acc[mi][2 * p + 1], ah[mi], bh[p][1], bh[p][3]);
                }
            #pragma unroll
            for (int mi = 0; mi < 2; mi++)
                #pragma unroll
                for (int p = 0; p < 2; p++) {
                    mma_bf16(acc[mi][2 * p + 0], ah[mi], bl[p][0], bl[p][2]);
                    mma_bf16(acc[mi][2 * p + 1], ah[mi], bl[p][1], bl[p][3]);
                }
            #pragma unroll
            for (int mi = 0; mi < 2; mi++)
                #pragma unroll
                for (int p = 0; p < 2; p++) {
                    mma_bf16(acc[mi][2 * p + 0], al[mi], bh[p][0], bh[p][2]);
                    mma_bf16(acc[mi][2 * p + 1], al[mi], bh[p][1], bh[p][3]);
                }
        }
    }

    // ---- epilogue: bias + scatter ----
    const int rq = lane >> 2, cq = (lane & 3) * 2;
    #pragma unroll
    for (int mi = 0; mi < 2; mi++) {
        const int rbase = m0 + wm * 32 + mi * 16 + rq;
        float* __restrict__ row0 = out + (size_t)rbase * NFULL;
        float* __restrict__ row1 = row0 + (size_t)8 * NFULL;
        #pragma unroll
        for (int nf = 0; nf < 4; nf++) {
            const int nl = wn * 32 + nf * 8 + cq;
            const float* c = acc[mi][nf];
            row0[s_oidx[nl]]     = c[0] + s_bias[nl];
            row0[s_oidx[nl + 1]] = c[1] + s_bias[nl + 1];
            row1[s_oidx[nl]]     = c[2] + s_bias[nl];
            row1[s_oidx[nl + 1]] = c[3] + s_bias[nl + 1];
        }
    }
}

// ---------------- launch ----------------
extern "C" void kernel_launch(void* const* d_in, const int* in_sizes, int n_in,
                              void* d_out, int out_size) {
    const float* x       = (const float*)d_in[0];
    const float* W       = (const float*)d_in[1];
    const float* b       = (const float*)d_in[2];
    const int*   in_idx  = (const int*)d_in[3];
    const int*   out_idx = (const int*)d_in[4];
    float*       out     = (float*)d_out;

    static bool attr_set = false;
    if (!attr_set) {
        cudaFuncSetAttribute(nsl_mma_gemm, cudaFuncAttributeMaxDynamicSharedMemorySize,
                             SMEM_BYTES);
        attr_set = true;
    }

    cudaMemsetAsync(out, 0, (size_t)out_size * sizeof(float), 0);

    build_pos_kernel<<<(NFULL + 255) / 256, 256>>>(in_idx);
    gather_split_kernel<<<MROWS / 4, 256>>>(x);
    split_w_kernel<<<(NACT * KACT / 4) / 256, 256>>>(W);

    dim3 grid(NACT / BN, MROWS / BM);   // (16, 64) = 1024 CTAs
    nsl_mma_gemm<<<grid, NTHREADS, SMEM_BYTES>>>(b, out_idx, out);
}

// round 7
// speedup vs baseline: 2.2085x; 1.0506x over previous
#include <cuda_runtime.h>
#include <cuda_bf16.h>
#include <cstdint>

// ---------------- problem constants ----------------
#define MROWS   8192
#define NFULL   4096
#define KACT    1024
#define NACT    1024

#define BM      128
#define BN      64
#define BKB     32                        // bf16 k-elements per stage chunk (64B/row)
#define NITER   (KACT / BKB)              // 32
#define STAGES  3
#define A_PLANE (128 * 64)                // 8192 B
#define B_PLANE (64 * 64)                 // 4096 B
#define STAGE_BYTES (2 * A_PLANE + 2 * B_PLANE)   // 24576
#define SMEM_BYTES  (STAGES * STAGE_BYTES)        // 73728
#define NTHREADS 256

// scratch planes: split-bf16 activations (gathered) and weights
__device__ __nv_bfloat16 g_xh[(size_t)MROWS * KACT];
__device__ __nv_bfloat16 g_xl[(size_t)MROWS * KACT];
__device__ __nv_bfloat16 g_wh[(size_t)NACT * KACT];
__device__ __nv_bfloat16 g_wl[(size_t)NACT * KACT];
__device__ int g_pos[NFULL];

// ---------------- helpers ----------------
__device__ __forceinline__ uint32_t smem_u32(const void* p) {
    uint32_t a;
    asm("{ .reg .u64 t; cvta.to.shared.u64 t, %1; cvt.u32.u64 %0, t; }" : "=r"(a) : "l"(p));
    return a;
}
__device__ __forceinline__ void cp_async16(uint32_t dst, const void* src) {
    asm volatile("cp.async.cg.shared.global [%0], [%1], 16;" :: "r"(dst), "l"(src));
}
__device__ __forceinline__ void ldsm4(uint32_t* r, uint32_t addr) {
    asm volatile("ldmatrix.sync.aligned.m8n8.x4.shared.b16 {%0,%1,%2,%3}, [%4];"
                 : "=r"(r[0]), "=r"(r[1]), "=r"(r[2]), "=r"(r[3]) : "r"(addr));
}
__device__ __forceinline__ void mma_bf16(float* d, const uint32_t* a,
                                         uint32_t b0, uint32_t b1) {
    asm volatile(
        "mma.sync.aligned.m16n8k16.row.col.f32.bf16.bf16.f32 "
        "{%0,%1,%2,%3}, {%4,%5,%6,%7}, {%8,%9}, {%0,%1,%2,%3};"
        : "+f"(d[0]), "+f"(d[1]), "+f"(d[2]), "+f"(d[3])
        : "r"(a[0]), "r"(a[1]), "r"(a[2]), "r"(a[3]), "r"(b0), "r"(b1));
}
__device__ __forceinline__ uint32_t pack_bf2(float a, float b) {
    __nv_bfloat162 t = __floats2bfloat162_rn(a, b);
    return *reinterpret_cast<uint32_t*>(&t);
}
// swizzled 16B-chunk offset within a 64B-row plane
__device__ __forceinline__ uint32_t swz(int r, int p) {
    return (uint32_t)(r * 64 + (((p + (r >> 1)) & 3) << 4));
}

// ---------------- kernel 1: inverse column map ----------------
__global__ void build_pos_kernel(const int* __restrict__ in_idx) {
    int c = blockIdx.x * blockDim.x + threadIdx.x;
    if (c >= NFULL) return;
    int lo = 0, hi = KACT - 1, found = -1;
    while (lo <= hi) {
        int mid = (lo + hi) >> 1;
        int v = __ldg(in_idx + mid);
        if (v == c) { found = mid; break; }
        if (v < c) lo = mid + 1; else hi = mid - 1;
    }
    g_pos[c] = found;
}

// ---------------- kernel 2: gather + bf16 split of x ----------------
__global__ __launch_bounds__(256) void gather_split_kernel(const float* __restrict__ x) {
    __shared__ int s_pos[NFULL];
    const int tid = threadIdx.x;
    for (int i = tid; i < NFULL; i += 256) s_pos[i] = g_pos[i];
    __syncthreads();

    const size_t r0 = (size_t)blockIdx.x * 4;
    const float4* __restrict__ x4 = (const float4*)x;
    #pragma unroll
    for (int i = 0; i < 16; i++) {
        int f = tid + i * 256;
        size_t row = r0 + (f >> 10);
        int c4 = f & 1023;
        float4 v = x4[row * (NFULL / 4) + c4];
        int c = c4 * 4;
        float vv[4] = {v.x, v.y, v.z, v.w};
        __nv_bfloat16* dh = g_xh + row * KACT;
        __nv_bfloat16* dl = g_xl + row * KACT;
        #pragma unroll
        for (int j = 0; j < 4; j++) {
            int p = s_pos[c + j];
            if (p >= 0) {
                __nv_bfloat16 h = __float2bfloat16_rn(vv[j]);
                dh[p] = h;
                dl[p] = __float2bfloat16_rn(vv[j] - __bfloat162float(h));
            }
        }
    }
}

// ---------------- kernel 3: bf16 split of W ----------------
__global__ __launch_bounds__(256) void split_w_kernel(const float* __restrict__ W) {
    int i = blockIdx.x * blockDim.x + threadIdx.x;
    float4 v = ((const float4*)W)[i];
    float h0 = __bfloat162float(__float2bfloat16_rn(v.x));
    float h1 = __bfloat162float(__float2bfloat16_rn(v.y));
    float h2 = __bfloat162float(__float2bfloat16_rn(v.z));
    float h3 = __bfloat162float(__float2bfloat16_rn(v.w));
    uint2 hp, lp;
    hp.x = pack_bf2(h0, h1);             hp.y = pack_bf2(h2, h3);
    lp.x = pack_bf2(v.x - h0, v.y - h1); lp.y = pack_bf2(v.z - h2, v.w - h3);
    ((uint2*)g_wh)[i] = hp;
    ((uint2*)g_wl)[i] = lp;
}

// ---------------- kernel 4: bf16x3 mma GEMM + bias + scatter ----------------
extern __shared__ char dynsmem[];

__global__ __launch_bounds__(NTHREADS, 3)
void nsl_mma_gemm(const float* __restrict__ bias, const int* __restrict__ out_idx,
                  float* __restrict__ out) {
    __shared__ float s_bias[BN];
    __shared__ int   s_oidx[BN];

    const int tid  = threadIdx.x;
    const int wid  = tid >> 5;
    const int lane = tid & 31;
    const int wm   = wid >> 1;        // 0..3 : 32-row band
    const int wn   = wid & 1;         // 0..1 : 32-col band
    const int m0   = blockIdx.y * BM;
    const int n0   = blockIdx.x * BN;

    if (tid < BN) {
        s_oidx[tid] = __ldg(out_idx + n0 + tid);
        s_bias[tid] = __ldg(bias + n0 + tid);
    }

    const uint32_t sbase = (smem_u32(dynsmem) + 127) & ~127u;
    const __nv_bfloat16* __restrict__ gAh = g_xh + (size_t)m0 * KACT;
    const __nv_bfloat16* __restrict__ gAl = g_xl + (size_t)m0 * KACT;
    const __nv_bfloat16* __restrict__ gBh = g_wh + (size_t)n0 * KACT;
    const __nv_bfloat16* __restrict__ gBl = g_wl + (size_t)n0 * KACT;

    // A plane: 128 rows x 4 chunks = 512 segs -> 2/thread (swizzled dst)
    auto load_planeA = [&](uint32_t dst, const __nv_bfloat16* src, int kc) {
        #pragma unroll
        for (int i = 0; i < 2; i++) {
            int s = tid + i * 256;
            int r = s >> 2, p = s & 3;
            cp_async16(dst + swz(r, p), src + (size_t)r * KACT + kc * BKB + p * 8);
        }
    };
    // B plane: 64 rows x 4 chunks = 256 segs -> 1/thread
    auto load_planeB = [&](uint32_t dst, const __nv_bfloat16* src, int kc) {
        int r = tid >> 2, p = tid & 3;
        cp_async16(dst + swz(r, p), src + (size_t)r * KACT + kc * BKB + p * 8);
    };
    auto load_stage = [&](int stage, int kc) {
        const uint32_t sb = sbase + stage * STAGE_BYTES;
        load_planeA(sb,               gAh, kc);
        load_planeA(sb + A_PLANE,     gAl, kc);
        load_planeB(sb + 2 * A_PLANE,           gBh, kc);
        load_planeB(sb + 2 * A_PLANE + B_PLANE, gBl, kc);
        asm volatile("cp.async.commit_group;");
    };

    // ldmatrix per-lane state: row offsets + two swizzled chunk offsets
    // row r = band + lrow; rot = (r>>1)&3 == (lrow>>1)&3 (bands are mult of 16)
    const int lrow = lane & 15;
    const int hi   = lane >> 4;                       // chunk half within k16
    const int rot  = (lrow >> 1) & 3;
    // chunk index for k-step kk: c = kk*2 + hi; swizzled -> ((c + rot)&3)<<4
    const uint32_t ch[2] = { (uint32_t)(((0 + hi + rot) & 3) << 4),
                             (uint32_t)(((2 + hi + rot) & 3) << 4) };
    uint32_t aRow[2], bRow[2];
    #pragma unroll
    for (int f = 0; f < 2; f++)
        aRow[f] = (uint32_t)((wm * 32 + f * 16 + lrow) * 64);
    #pragma unroll
    for (int p = 0; p < 2; p++)
        bRow[p] = (uint32_t)(2 * A_PLANE + (wn * 32 + p * 16 + lrow) * 64);

    float acc[2][4][4];
    #pragma unroll
    for (int i = 0; i < 2; i++)
        #pragma unroll
        for (int j = 0; j < 4; j++)
            #pragma unroll
            for (int q = 0; q < 4; q++) acc[i][j][q] = 0.f;

    load_stage(0, 0);
    load_stage(1, 1);

    for (int t = 0; t < NITER; t++) {
        if (t < NITER - 1) asm volatile("cp.async.wait_group 1;" ::: "memory");
        else               asm volatile("cp.async.wait_group 0;" ::: "memory");
        __syncthreads();
        // slot (t+2)%3 == (t-1)%3 was consumed last iteration -> safe to refill now
        if (t + 2 < NITER) load_stage((t + 2) % STAGES, t + 2);

        const uint32_t sb = sbase + (t % STAGES) * STAGE_BYTES;
        #pragma unroll
        for (int kk = 0; kk < 2; kk++) {            // 2 x k16 steps
            const uint32_t co = ch[kk];
            uint32_t ah[2][4], al[2][4], bh[2][4], bl[2][4];
            ldsm4(ah[0], sb + aRow[0] + co);
            ldsm4(ah[1], sb + aRow[1] + co);
            ldsm4(al[0], sb + A_PLANE + aRow[0] + co);
            ldsm4(al[1], sb + A_PLANE + aRow[1] + co);
            ldsm4(bh[0], sb + bRow[0] + co);
            ldsm4(bh[1], sb + bRow[1] + co);
            ldsm4(bl[0], sb + B_PLANE + bRow[0] + co);
            ldsm4(bl[1], sb + B_PLANE + bRow[1] + co);

            // term-major: max dependency distance on each accumulator
            #pragma unroll
            for (int mi = 0; mi < 2; mi++)
                #pragma unroll
                for (int p = 0; p < 2; p++) {
                    mma_bf16(acc[mi][2 * p + 0], ah[mi], bh[p][0], bh[p][2]);
                    mma_bf16(acc[mi][2 * p + 1], ah[mi], bh[p][1], bh[p][3]);
                }
            #pragma unroll
            for (int mi = 0; mi < 2; mi++)
                #pragma unroll
                for (int p = 0; p < 2; p++) {
                    mma_bf16(acc[mi][2 * p + 0], ah[mi], bl[p][0], bl[p][2]);
                    mma_bf16(acc[mi][2 * p + 1], ah[mi], bl[p][1], bl[p][3]);
                }
            #pragma unroll
            for (int mi = 0; mi < 2; mi++)
                #pragma unroll
                for (int p = 0; p < 2; p++) {
                    mma_bf16(acc[mi][2 * p + 0], al[mi], bh[p][0], bh[p][2]);
                    mma_bf16(acc[mi][2 * p + 1], al[mi], bh[p][1], bh[p][3]);
                }
        }
    }

    // ---- epilogue: bias + scatter ----
    const int rq = lane >> 2, cq = (lane & 3) * 2;
    #pragma unroll
    for (int mi = 0; mi < 2; mi++) {
        const int rbase = m0 + wm * 32 + mi * 16 + rq;
        float* __restrict__ row0 = out + (size_t)rbase * NFULL;
        float* __restrict__ row1 = row0 + (size_t)8 * NFULL;
        #pragma unroll
        for (int nf = 0; nf < 4; nf++) {
            const int nl = wn * 32 + nf * 8 + cq;
            const float* c = acc[mi][nf];
            row0[s_oidx[nl]]     = c[0] + s_bias[nl];
            row0[s_oidx[nl + 1]] = c[1] + s_bias[nl + 1];
            row1[s_oidx[nl]]     = c[2] + s_bias[nl];
            row1[s_oidx[nl + 1]] = c[3] + s_bias[nl + 1];
        }
    }
}

// ---------------- launch ----------------
extern "C" void kernel_launch(void* const* d_in, const int* in_sizes, int n_in,
                              void* d_out, int out_size) {
    const float* x       = (const float*)d_in[0];
    const float* W       = (const float*)d_in[1];
    const float* b       = (const float*)d_in[2];
    const int*   in_idx  = (const int*)d_in[3];
    const int*   out_idx = (const int*)d_in[4];
    float*       out     = (float*)d_out;

    static bool attr_set = false;
    if (!attr_set) {
        cudaFuncSetAttribute(nsl_mma_gemm, cudaFuncAttributeMaxDynamicSharedMemorySize,
                             SMEM_BYTES + 128);
        attr_set = true;
    }

    cudaMemsetAsync(out, 0, (size_t)out_size * sizeof(float), 0);

    build_pos_kernel<<<(NFULL + 255) / 256, 256>>>(in_idx);
    gather_split_kernel<<<MROWS / 4, 256>>>(x);
    split_w_kernel<<<(NACT * KACT / 4) / 256, 256>>>(W);

    dim3 grid(NACT / BN, MROWS / BM);   // (16, 64) = 1024 CTAs
    nsl_mma_gemm<<<grid, NTHREADS, SMEM_BYTES + 128>>>(b, out_idx, out);
}

// round 8
// speedup vs baseline: 2.4689x; 1.1179x over previous
#include <cuda_runtime.h>
#include <cuda_bf16.h>
#include <cstdint>

// ---------------- problem constants ----------------
#define MROWS   8192
#define NFULL   4096
#define KACT    1024
#define NACT    1024

#define BM      64
#define BN      64
#define BKB     32                        // bf16 k-elements per stage chunk (64B/row)
#define NITER   (KACT / BKB)              // 32
#define STAGES  3
#define A_PLANE (64 * 64)                 // 4096 B
#define B_PLANE (64 * 64)                 // 4096 B
#define STAGE_BYTES (2 * A_PLANE + 2 * B_PLANE)   // 16384
#define SMEM_BYTES  (STAGES * STAGE_BYTES)        // 49152
#define NTHREADS 256

// scratch planes: split-bf16 activations (gathered) and weights
__device__ __nv_bfloat16 g_xh[(size_t)MROWS * KACT];
__device__ __nv_bfloat16 g_xl[(size_t)MROWS * KACT];
__device__ __nv_bfloat16 g_wh[(size_t)NACT * KACT];
__device__ __nv_bfloat16 g_wl[(size_t)NACT * KACT];
__device__ int g_pos[NFULL];

// ---------------- helpers ----------------
__device__ __forceinline__ uint32_t smem_u32(const void* p) {
    uint32_t a;
    asm("{ .reg .u64 t; cvta.to.shared.u64 t, %1; cvt.u32.u64 %0, t; }" : "=r"(a) : "l"(p));
    return a;
}
__device__ __forceinline__ void cp_async16(uint32_t dst, const void* src) {
    asm volatile("cp.async.cg.shared.global [%0], [%1], 16;" :: "r"(dst), "l"(src));
}
__device__ __forceinline__ void ldsm4(uint32_t* r, uint32_t addr) {
    asm volatile("ldmatrix.sync.aligned.m8n8.x4.shared.b16 {%0,%1,%2,%3}, [%4];"
                 : "=r"(r[0]), "=r"(r[1]), "=r"(r[2]), "=r"(r[3]) : "r"(addr));
}
__device__ __forceinline__ void mma_bf16(float* d, const uint32_t* a,
                                         uint32_t b0, uint32_t b1) {
    asm volatile(
        "mma.sync.aligned.m16n8k16.row.col.f32.bf16.bf16.f32 "
        "{%0,%1,%2,%3}, {%4,%5,%6,%7}, {%8,%9}, {%0,%1,%2,%3};"
        : "+f"(d[0]), "+f"(d[1]), "+f"(d[2]), "+f"(d[3])
        : "r"(a[0]), "r"(a[1]), "r"(a[2]), "r"(a[3]), "r"(b0), "r"(b1));
}
__device__ __forceinline__ uint32_t pack_bf2(float a, float b) {
    __nv_bfloat162 t = __floats2bfloat162_rn(a, b);
    return *reinterpret_cast<uint32_t*>(&t);
}
// swizzled 16B-chunk offset within a 64B-row plane
__device__ __forceinline__ uint32_t swz(int r, int p) {
    return (uint32_t)(r * 64 + (((p + (r >> 1)) & 3) << 4));
}

// ---------------- kernel 1: inverse column map ----------------
__global__ void build_pos_kernel(const int* __restrict__ in_idx) {
    int c = blockIdx.x * blockDim.x + threadIdx.x;
    if (c >= NFULL) return;
    int lo = 0, hi = KACT - 1, found = -1;
    while (lo <= hi) {
        int mid = (lo + hi) >> 1;
        int v = __ldg(in_idx + mid);
        if (v == c) { found = mid; break; }
        if (v < c) lo = mid + 1; else hi = mid - 1;
    }
    g_pos[c] = found;
}

// ---------------- kernel 2: gather + bf16 split of x ----------------
__global__ __launch_bounds__(256) void gather_split_kernel(const float* __restrict__ x) {
    __shared__ int s_pos[NFULL];
    const int tid = threadIdx.x;
    for (int i = tid; i < NFULL; i += 256) s_pos[i] = g_pos[i];
    __syncthreads();

    const size_t r0 = (size_t)blockIdx.x * 4;
    const float4* __restrict__ x4 = (const float4*)x;
    #pragma unroll
    for (int i = 0; i < 16; i++) {
        int f = tid + i * 256;
        size_t row = r0 + (f >> 10);
        int c4 = f & 1023;
        float4 v = x4[row * (NFULL / 4) + c4];
        int c = c4 * 4;
        float vv[4] = {v.x, v.y, v.z, v.w};
        __nv_bfloat16* dh = g_xh + row * KACT;
        __nv_bfloat16* dl = g_xl + row * KACT;
        #pragma unroll
        for (int j = 0; j < 4; j++) {
            int p = s_pos[c + j];
            if (p >= 0) {
                __nv_bfloat16 h = __float2bfloat16_rn(vv[j]);
                dh[p] = h;
                dl[p] = __float2bfloat16_rn(vv[j] - __bfloat162float(h));
            }
        }
    }
}

// ---------------- kernel 3: bf16 split of W ----------------
__global__ __launch_bounds__(256) void split_w_kernel(const float* __restrict__ W) {
    int i = blockIdx.x * blockDim.x + threadIdx.x;
    float4 v = ((const float4*)W)[i];
    float h0 = __bfloat162float(__float2bfloat16_rn(v.x));
    float h1 = __bfloat162float(__float2bfloat16_rn(v.y));
    float h2 = __bfloat162float(__float2bfloat16_rn(v.z));
    float h3 = __bfloat162float(__float2bfloat16_rn(v.w));
    uint2 hp, lp;
    hp.x = pack_bf2(h0, h1);             hp.y = pack_bf2(h2, h3);
    lp.x = pack_bf2(v.x - h0, v.y - h1); lp.y = pack_bf2(v.z - h2, v.w - h3);
    ((uint2*)g_wh)[i] = hp;
    ((uint2*)g_wl)[i] = lp;
}

// ---------------- kernel 4: bf16x3 mma GEMM + bias + scatter ----------------
extern __shared__ char dynsmem[];

__global__ __launch_bounds__(NTHREADS, 4)
void nsl_mma_gemm(const float* __restrict__ bias, const int* __restrict__ out_idx,
                  float* __restrict__ out) {
    __shared__ float s_bias[BN];
    __shared__ int   s_oidx[BN];

    const int tid  = threadIdx.x;
    const int wid  = tid >> 5;
    const int lane = tid & 31;
    const int wm   = wid & 1;         // 0..1 : 32-row band
    const int wn   = wid >> 1;        // 0..3 : 16-col band
    const int m0   = blockIdx.y * BM;
    const int n0   = blockIdx.x * BN;

    if (tid < BN) {
        s_oidx[tid] = __ldg(out_idx + n0 + tid);
        s_bias[tid] = __ldg(bias + n0 + tid);
    }

    const uint32_t sbase = (smem_u32(dynsmem) + 127) & ~127u;

    // per-thread load assignment: one 16B seg per plane per stage
    const int r = tid >> 2, p = tid & 3;
    const size_t goff = (size_t)r * KACT + p * 8;
    const __nv_bfloat16* __restrict__ srcAh = g_xh + (size_t)m0 * KACT + goff;
    const __nv_bfloat16* __restrict__ srcAl = g_xl + (size_t)m0 * KACT + goff;
    const __nv_bfloat16* __restrict__ srcBh = g_wh + (size_t)n0 * KACT + goff;
    const __nv_bfloat16* __restrict__ srcBl = g_wl + (size_t)n0 * KACT + goff;
    const uint32_t dsw = swz(r, p);

    auto load_stage = [&](int stage, int kc) {
        const uint32_t sb = sbase + stage * STAGE_BYTES + dsw;
        const int ko = kc * BKB;
        cp_async16(sb,                         srcAh + ko);
        cp_async16(sb + A_PLANE,               srcAl + ko);
        cp_async16(sb + 2 * A_PLANE,           srcBh + ko);
        cp_async16(sb + 2 * A_PLANE + B_PLANE, srcBl + ko);
        asm volatile("cp.async.commit_group;");
    };

    // ldmatrix per-lane state
    const int lrow = lane & 15;
    const int hi   = lane >> 4;
    const int rot  = (lrow >> 1) & 3;
    const uint32_t ch[2] = { (uint32_t)(((0 + hi + rot) & 3) << 4),
                             (uint32_t)(((2 + hi + rot) & 3) << 4) };
    uint32_t aRow[2];
    #pragma unroll
    for (int f = 0; f < 2; f++)
        aRow[f] = (uint32_t)((wm * 32 + f * 16 + lrow) * 64);
    const uint32_t bRow = (uint32_t)(2 * A_PLANE + (wn * 16 + lrow) * 64);

    float acc[2][2][4];
    #pragma unroll
    for (int i = 0; i < 2; i++)
        #pragma unroll
        for (int j = 0; j < 2; j++)
            #pragma unroll
            for (int q = 0; q < 4; q++) acc[i][j][q] = 0.f;

    load_stage(0, 0);
    load_stage(1, 1);

    for (int t = 0; t < NITER; t++) {
        if (t < NITER - 1) asm volatile("cp.async.wait_group 1;" ::: "memory");
        else               asm volatile("cp.async.wait_group 0;" ::: "memory");
        __syncthreads();
        // slot (t+2)%3 == (t-1)%3 was consumed last iteration -> safe to refill now
        if (t + 2 < NITER) load_stage((t + 2) % STAGES, t + 2);

        const uint32_t sb = sbase + (t % STAGES) * STAGE_BYTES;
        #pragma unroll
        for (int kk = 0; kk < 2; kk++) {            // 2 x k16 steps
            const uint32_t co = ch[kk];
            uint32_t ah[2][4], al[2][4], bh[4], bl[4];
            ldsm4(ah[0], sb + aRow[0] + co);
            ldsm4(ah[1], sb + aRow[1] + co);
            ldsm4(al[0], sb + A_PLANE + aRow[0] + co);
            ldsm4(al[1], sb + A_PLANE + aRow[1] + co);
            ldsm4(bh,    sb + bRow + co);
            ldsm4(bl,    sb + B_PLANE + bRow + co);

            // term-major: max dependency distance on each accumulator
            #pragma unroll
            for (int mi = 0; mi < 2; mi++) {
                mma_bf16(acc[mi][0], ah[mi], bh[0], bh[2]);
                mma_bf16(acc[mi][1], ah[mi], bh[1], bh[3]);
            }
            #pragma unroll
            for (int mi = 0; mi < 2; mi++) {
                mma_bf16(acc[mi][0], ah[mi], bl[0], bl[2]);
                mma_bf16(acc[mi][1], ah[mi], bl[1], bl[3]);
            }
            #pragma unroll
            for (int mi = 0; mi < 2; mi++) {
                mma_bf16(acc[mi][0], al[mi], bh[0], bh[2]);
                mma_bf16(acc[mi][1], al[mi], bh[1], bh[3]);
            }
        }
    }

    // ---- epilogue: bias + scatter ----
    const int rq = lane >> 2, cq = (lane & 3) * 2;
    #pragma unroll
    for (int mi = 0; mi < 2; mi++) {
        const int rbase = m0 + wm * 32 + mi * 16 + rq;
        float* __restrict__ row0 = out + (size_t)rbase * NFULL;
        float* __restrict__ row1 = row0 + (size_t)8 * NFULL;
        #pragma unroll
        for (int nf = 0; nf < 2; nf++) {
            const int nl = wn * 16 + nf * 8 + cq;
            const float* c = acc[mi][nf];
            row0[s_oidx[nl]]     = c[0] + s_bias[nl];
            row0[s_oidx[nl + 1]] = c[1] + s_bias[nl + 1];
            row1[s_oidx[nl]]     = c[2] + s_bias[nl];
            row1[s_oidx[nl + 1]] = c[3] + s_bias[nl + 1];
        }
    }
}

// ---------------- launch ----------------
extern "C" void kernel_launch(void* const* d_in, const int* in_sizes, int n_in,
                              void* d_out, int out_size) {
    const float* x       = (const float*)d_in[0];
    const float* W       = (const float*)d_in[1];
    const float* b       = (const float*)d_in[2];
    const int*   in_idx  = (const int*)d_in[3];
    const int*   out_idx = (const int*)d_in[4];
    float*       out     = (float*)d_out;

    static bool attr_set = false;
    if (!attr_set) {
        cudaFuncSetAttribute(nsl_mma_gemm, cudaFuncAttributeMaxDynamicSharedMemorySize,
                             SMEM_BYTES + 128);
        attr_set = true;
    }

    cudaMemsetAsync(out, 0, (size_t)out_size * sizeof(float), 0);

    build_pos_kernel<<<(NFULL + 255) / 256, 256>>>(in_idx);
    gather_split_kernel<<<MROWS / 4, 256>>>(x);
    split_w_kernel<<<(NACT * KACT / 4) / 256, 256>>>(W);

    dim3 grid(NACT / BN, MROWS / BM);   // (16, 128) = 2048 CTAs
    nsl_mma_gemm<<<grid, NTHREADS, SMEM_BYTES + 128>>>(b, out_idx, out);
}

// round 9
// speedup vs baseline: 2.4729x; 1.0016x over previous
#include <cuda_runtime.h>
#include <cuda_bf16.h>
#include <cstdint>

// ---------------- problem constants ----------------
#define MROWS   8192
#define NFULL   4096
#define KACT    1024
#define NACT    1024

#define BM      64
#define BN      64
#define BKB     32                        // bf16 k-elements per stage chunk (64B/row)
#define NITER   (KACT / BKB)              // 32
#define STAGES  3
#define A_PLANE (64 * 64)                 // 4096 B
#define B_PLANE (64 * 64)                 // 4096 B
#define STAGE_BYTES (2 * A_PLANE + 2 * B_PLANE)   // 16384
#define SMEM_BYTES  (STAGES * STAGE_BYTES)        // 49152
#define NTHREADS 256

// scratch planes: split-bf16 activations (gathered) and weights
__device__ __nv_bfloat16 g_xh[(size_t)MROWS * KACT];
__device__ __nv_bfloat16 g_xl[(size_t)MROWS * KACT];
__device__ __nv_bfloat16 g_wh[(size_t)NACT * KACT];
__device__ __nv_bfloat16 g_wl[(size_t)NACT * KACT];
__device__ int g_pos[NFULL];

// ---------------- helpers ----------------
__device__ __forceinline__ uint32_t smem_u32(const void* p) {
    uint32_t a;
    asm("{ .reg .u64 t; cvta.to.shared.u64 t, %1; cvt.u32.u64 %0, t; }" : "=r"(a) : "l"(p));
    return a;
}
__device__ __forceinline__ void cp_async16(uint32_t dst, const void* src) {
    asm volatile("cp.async.cg.shared.global [%0], [%1], 16;" :: "r"(dst), "l"(src));
}
__device__ __forceinline__ void ldsm4(uint32_t* r, uint32_t addr) {
    asm volatile("ldmatrix.sync.aligned.m8n8.x4.shared.b16 {%0,%1,%2,%3}, [%4];"
                 : "=r"(r[0]), "=r"(r[1]), "=r"(r[2]), "=r"(r[3]) : "r"(addr));
}
__device__ __forceinline__ void mma_bf16(float* d, const uint32_t* a,
                                         uint32_t b0, uint32_t b1) {
    asm volatile(
        "mma.sync.aligned.m16n8k16.row.col.f32.bf16.bf16.f32 "
        "{%0,%1,%2,%3}, {%4,%5,%6,%7}, {%8,%9}, {%0,%1,%2,%3};"
        : "+f"(d[0]), "+f"(d[1]), "+f"(d[2]), "+f"(d[3])
        : "r"(a[0]), "r"(a[1]), "r"(a[2]), "r"(a[3]), "r"(b0), "r"(b1));
}
__device__ __forceinline__ uint32_t pack_bf2(float a, float b) {
    __nv_bfloat162 t = __floats2bfloat162_rn(a, b);
    return *reinterpret_cast<uint32_t*>(&t);
}
// swizzled 16B-chunk offset within a 64B-row plane
__device__ __forceinline__ uint32_t swz(int r, int p) {
    return (uint32_t)(r * 64 + (((p + (r >> 1)) & 3) << 4));
}

// ---------------- kernel 1: inverse column map ----------------
__global__ void build_pos_kernel(const int* __restrict__ in_idx) {
    int c = blockIdx.x * blockDim.x + threadIdx.x;
    if (c >= NFULL) return;
    int lo = 0, hi = KACT - 1, found = -1;
    while (lo <= hi) {
        int mid = (lo + hi) >> 1;
        int v = __ldg(in_idx + mid);
        if (v == c) { found = mid; break; }
        if (v < c) lo = mid + 1; else hi = mid - 1;
    }
    g_pos[c] = found;
}

// ---------------- kernel 2: gather + bf16 split of x ----------------
__global__ __launch_bounds__(256) void gather_split_kernel(const float* __restrict__ x) {
    __shared__ int s_pos[NFULL];
    const int tid = threadIdx.x;
    for (int i = tid; i < NFULL; i += 256) s_pos[i] = g_pos[i];
    __syncthreads();

    const size_t r0 = (size_t)blockIdx.x * 4;
    const float4* __restrict__ x4 = (const float4*)x;
    #pragma unroll
    for (int i = 0; i < 16; i++) {
        int f = tid + i * 256;
        size_t row = r0 + (f >> 10);
        int c4 = f & 1023;
        float4 v = x4[row * (NFULL / 4) + c4];
        int c = c4 * 4;
        float vv[4] = {v.x, v.y, v.z, v.w};
        __nv_bfloat16* dh = g_xh + row * KACT;
        __nv_bfloat16* dl = g_xl + row * KACT;
        #pragma unroll
        for (int j = 0; j < 4; j++) {
            int p = s_pos[c + j];
            if (p >= 0) {
                __nv_bfloat16 h = __float2bfloat16_rn(vv[j]);
                dh[p] = h;
                dl[p] = __float2bfloat16_rn(vv[j] - __bfloat162float(h));
            }
        }
    }
}

// ---------------- kernel 3: bf16 split of W ----------------
__global__ __launch_bounds__(256) void split_w_kernel(const float* __restrict__ W) {
    int i = blockIdx.x * blockDim.x + threadIdx.x;
    float4 v = ((const float4*)W)[i];
    float h0 = __bfloat162float(__float2bfloat16_rn(v.x));
    float h1 = __bfloat162float(__float2bfloat16_rn(v.y));
    float h2 = __bfloat162float(__float2bfloat16_rn(v.z));
    float h3 = __bfloat162float(__float2bfloat16_rn(v.w));
    uint2 hp, lp;
    hp.x = pack_bf2(h0, h1);             hp.y = pack_bf2(h2, h3);
    lp.x = pack_bf2(v.x - h0, v.y - h1); lp.y = pack_bf2(v.z - h2, v.w - h3);
    ((uint2*)g_wh)[i] = hp;
    ((uint2*)g_wl)[i] = lp;
}

// ---------------- kernel 4: bf16x3 mma GEMM + bias + scatter ----------------
extern __shared__ char dynsmem[];

__global__ __launch_bounds__(NTHREADS, 4)
void nsl_mma_gemm(const float* __restrict__ bias, const int* __restrict__ out_idx,
                  float* __restrict__ out) {
    __shared__ float s_bias[BN];
    __shared__ int   s_oidx[BN];

    const int tid  = threadIdx.x;
    const int wid  = tid >> 5;
    const int lane = tid & 31;
    const int wm   = wid & 1;         // 0..1 : 32-row band
    const int wn   = wid >> 1;        // 0..3 : 16-col band
    const int m0   = blockIdx.y * BM;
    const int n0   = blockIdx.x * BN;

    if (tid < BN) {
        s_oidx[tid] = __ldg(out_idx + n0 + tid);
        s_bias[tid] = __ldg(bias + n0 + tid);
    }

    const uint32_t sbase = (smem_u32(dynsmem) + 127) & ~127u;

    // per-thread load assignment: one 16B seg per plane per stage
    const int r = tid >> 2, p = tid & 3;
    const size_t goff = (size_t)r * KACT + p * 8;
    const __nv_bfloat16* __restrict__ srcAh = g_xh + (size_t)m0 * KACT + goff;
    const __nv_bfloat16* __restrict__ srcAl = g_xl + (size_t)m0 * KACT + goff;
    const __nv_bfloat16* __restrict__ srcBh = g_wh + (size_t)n0 * KACT + goff;
    const __nv_bfloat16* __restrict__ srcBl = g_wl + (size_t)n0 * KACT + goff;
    const uint32_t dsw = swz(r, p);

    auto load_stage = [&](int stage, int kc) {
        const uint32_t sb = sbase + stage * STAGE_BYTES + dsw;
        const int ko = kc * BKB;
        cp_async16(sb,                         srcAh + ko);
        cp_async16(sb + A_PLANE,               srcAl + ko);
        cp_async16(sb + 2 * A_PLANE,           srcBh + ko);
        cp_async16(sb + 2 * A_PLANE + B_PLANE, srcBl + ko);
        asm volatile("cp.async.commit_group;");
    };

    // ldmatrix per-lane state
    const int lrow = lane & 15;
    const int hi   = lane >> 4;
    const int rot  = (lrow >> 1) & 3;
    const uint32_t ch[2] = { (uint32_t)(((0 + hi + rot) & 3) << 4),
                             (uint32_t)(((2 + hi + rot) & 3) << 4) };
    uint32_t aRow[2];
    #pragma unroll
    for (int f = 0; f < 2; f++)
        aRow[f] = (uint32_t)((wm * 32 + f * 16 + lrow) * 64);
    const uint32_t bRow = (uint32_t)(2 * A_PLANE + (wn * 16 + lrow) * 64);

    float acc[2][2][4];
    #pragma unroll
    for (int i = 0; i < 2; i++)
        #pragma unroll
        for (int j = 0; j < 2; j++)
            #pragma unroll
            for (int q = 0; q < 4; q++) acc[i][j][q] = 0.f;

    load_stage(0, 0);
    load_stage(1, 1);

    for (int t = 0; t < NITER; t++) {
        if (t < NITER - 1) asm volatile("cp.async.wait_group 1;" ::: "memory");
        else               asm volatile("cp.async.wait_group 0;" ::: "memory");
        __syncthreads();
        // slot (t+2)%3 == (t-1)%3 was consumed last iteration -> safe to refill now
        if (t + 2 < NITER) load_stage((t + 2) % STAGES, t + 2);

        const uint32_t sb = sbase + (t % STAGES) * STAGE_BYTES;
        #pragma unroll
        for (int kk = 0; kk < 2; kk++) {            // 2 x k16 steps
            const uint32_t co = ch[kk];
            uint32_t ah[2][4], al[2][4], bh[4], bl[4];
            ldsm4(ah[0], sb + aRow[0] + co);
            ldsm4(ah[1], sb + aRow[1] + co);
            ldsm4(al[0], sb + A_PLANE + aRow[0] + co);
            ldsm4(al[1], sb + A_PLANE + aRow[1] + co);
            ldsm4(bh,    sb + bRow + co);
            ldsm4(bl,    sb + B_PLANE + bRow + co);

            // term-major: max dependency distance on each accumulator
            #pragma unroll
            for (int mi = 0; mi < 2; mi++) {
                mma_bf16(acc[mi][0], ah[mi], bh[0], bh[2]);
                mma_bf16(acc[mi][1], ah[mi], bh[1], bh[3]);
            }
            #pragma unroll
            for (int mi = 0; mi < 2; mi++) {
                mma_bf16(acc[mi][0], ah[mi], bl[0], bl[2]);
                mma_bf16(acc[mi][1], ah[mi], bl[1], bl[3]);
            }
            #pragma unroll
            for (int mi = 0; mi < 2; mi++) {
                mma_bf16(acc[mi][0], al[mi], bh[0], bh[2]);
                mma_bf16(acc[mi][1], al[mi], bh[1], bh[3]);
            }
        }
    }

    // ---- epilogue: bias + scatter ----
    const int rq = lane >> 2, cq = (lane & 3) * 2;
    #pragma unroll
    for (int mi = 0; mi < 2; mi++) {
        const int rbase = m0 + wm * 32 + mi * 16 + rq;
        float* __restrict__ row0 = out + (size_t)rbase * NFULL;
        float* __restrict__ row1 = row0 + (size_t)8 * NFULL;
        #pragma unroll
        for (int nf = 0; nf < 2; nf++) {
            const int nl = wn * 16 + nf * 8 + cq;
            const float* c = acc[mi][nf];
            row0[s_oidx[nl]]     = c[0] + s_bias[nl];
            row0[s_oidx[nl + 1]] = c[1] + s_bias[nl + 1];
            row1[s_oidx[nl]]     = c[2] + s_bias[nl];
            row1[s_oidx[nl + 1]] = c[3] + s_bias[nl + 1];
        }
    }
}

// ---------------- launch: fork-join across streams (graph-capturable) ----------------
extern "C" void kernel_launch(void* const* d_in, const int* in_sizes, int n_in,
                              void* d_out, int out_size) {
    const float* x       = (const float*)d_in[0];
    const float* W       = (const float*)d_in[1];
    const float* b       = (const float*)d_in[2];
    const int*   in_idx  = (const int*)d_in[3];
    const int*   out_idx = (const int*)d_in[4];
    float*       out     = (float*)d_out;

    static bool init_done = false;
    static cudaStream_t s1, s2;
    static cudaEvent_t  eFork, eMemset, eSplitW;
    if (!init_done) {
        cudaFuncSetAttribute(nsl_mma_gemm, cudaFuncAttributeMaxDynamicSharedMemorySize,
                             SMEM_BYTES + 128);
        cudaStreamCreateWithFlags(&s1, cudaStreamNonBlocking);
        cudaStreamCreateWithFlags(&s2, cudaStreamNonBlocking);
        cudaEventCreateWithFlags(&eFork,   cudaEventDisableTiming);
        cudaEventCreateWithFlags(&eMemset, cudaEventDisableTiming);
        cudaEventCreateWithFlags(&eSplitW, cudaEventDisableTiming);
        init_done = true;
    }

    // fork: s1 = memset (zero-fill output), s2 = split_w, main = build_pos -> gather
    cudaEventRecord(eFork, 0);
    cudaStreamWaitEvent(s1, eFork, 0);
    cudaStreamWaitEvent(s2, eFork, 0);

    cudaMemsetAsync(out, 0, (size_t)out_size * sizeof(float), s1);
    cudaEventRecord(eMemset, s1);

    split_w_kernel<<<(NACT * KACT / 4) / 256, 256, 0, s2>>>(W);
    cudaEventRecord(eSplitW, s2);

    build_pos_kernel<<<(NFULL + 255) / 256, 256>>>(in_idx);
    gather_split_kernel<<<MROWS / 4, 256>>>(x);

    // join: GEMM needs gather (stream 0), split_w (s2), memset (s1, for epilogue writes)
    cudaStreamWaitEvent(0, eMemset, 0);
    cudaStreamWaitEvent(0, eSplitW, 0);

    dim3 grid(NACT / BN, MROWS / BM);   // (16, 128) = 2048 CTAs
    nsl_mma_gemm<<<grid, NTHREADS, SMEM_BYTES + 128>>>(b, out_idx, out);
}

// round 10
// speedup vs baseline: 2.9995x; 1.2130x over previous
#include <cuda_runtime.h>
#include <cuda_fp16.h>
#include <cstdint>

// ---------------- problem constants ----------------
#define MROWS   8192
#define NFULL   4096
#define KACT    1024
#define NACT    1024

#define BM      64
#define BN      64
#define BKB     32                        // fp16 k-elements per stage chunk (64B/row)
#define NITER   (KACT / BKB)              // 32
#define STAGES  3
#define A_PLANE (64 * 64)                 // 4096 B (x fp16)
#define B_PLANE (64 * 64)                 // 4096 B (w hi / lo fp16)
#define STAGE_BYTES (A_PLANE + 2 * B_PLANE)       // 12288
#define SMEM_BYTES  (STAGES * STAGE_BYTES)        // 36864
#define NTHREADS 256

#define WSCALE     2048.0f
#define INV_WSCALE (1.0f / 2048.0f)

// scratch planes: gathered fp16 activations, split fp16 weights (x WSCALE)
__device__ __half g_xa[(size_t)MROWS * KACT];
__device__ __half g_wh[(size_t)NACT * KACT];
__device__ __half g_wl[(size_t)NACT * KACT];
__device__ int    g_pos[NFULL];

// ---------------- helpers ----------------
__device__ __forceinline__ uint32_t smem_u32(const void* p) {
    uint32_t a;
    asm("{ .reg .u64 t; cvta.to.shared.u64 t, %1; cvt.u32.u64 %0, t; }" : "=r"(a) : "l"(p));
    return a;
}
__device__ __forceinline__ void cp_async16(uint32_t dst, const void* src) {
    asm volatile("cp.async.cg.shared.global [%0], [%1], 16;" :: "r"(dst), "l"(src));
}
__device__ __forceinline__ void ldsm4(uint32_t* r, uint32_t addr) {
    asm volatile("ldmatrix.sync.aligned.m8n8.x4.shared.b16 {%0,%1,%2,%3}, [%4];"
                 : "=r"(r[0]), "=r"(r[1]), "=r"(r[2]), "=r"(r[3]) : "r"(addr));
}
__device__ __forceinline__ void mma_f16(float* d, const uint32_t* a,
                                        uint32_t b0, uint32_t b1) {
    asm volatile(
        "mma.sync.aligned.m16n8k16.row.col.f32.f16.f16.f32 "
        "{%0,%1,%2,%3}, {%4,%5,%6,%7}, {%8,%9}, {%0,%1,%2,%3};"
        : "+f"(d[0]), "+f"(d[1]), "+f"(d[2]), "+f"(d[3])
        : "r"(a[0]), "r"(a[1]), "r"(a[2]), "r"(a[3]), "r"(b0), "r"(b1));
}
__device__ __forceinline__ uint32_t pack_h2(float a, float b) {
    __half2 t = __floats2half2_rn(a, b);
    return *reinterpret_cast<uint32_t*>(&t);
}
// swizzled 16B-chunk offset within a 64B-row plane
__device__ __forceinline__ uint32_t swz(int r, int p) {
    return (uint32_t)(r * 64 + (((p + (r >> 1)) & 3) << 4));
}

// ---------------- kernel 1: inverse column map ----------------
__global__ void build_pos_kernel(const int* __restrict__ in_idx) {
    int c = blockIdx.x * blockDim.x + threadIdx.x;
    if (c >= NFULL) return;
    int lo = 0, hi = KACT - 1, found = -1;
    while (lo <= hi) {
        int mid = (lo + hi) >> 1;
        int v = __ldg(in_idx + mid);
        if (v == c) { found = mid; break; }
        if (v < c) lo = mid + 1; else hi = mid - 1;
    }
    g_pos[c] = found;
}

// ---------------- kernel 2: gather x[:, in_idx] -> fp16 plane ----------------
__global__ __launch_bounds__(256) void gather_kernel(const float* __restrict__ x) {
    __shared__ int s_pos[NFULL];
    const int tid = threadIdx.x;
    for (int i = tid; i < NFULL; i += 256) s_pos[i] = g_pos[i];
    __syncthreads();

    const size_t r0 = (size_t)blockIdx.x * 4;
    const float4* __restrict__ x4 = (const float4*)x;
    #pragma unroll
    for (int i = 0; i < 16; i++) {
        int f = tid + i * 256;
        size_t row = r0 + (f >> 10);
        int c4 = f & 1023;
        float4 v = x4[row * (NFULL / 4) + c4];
        int c = c4 * 4;
        float vv[4] = {v.x, v.y, v.z, v.w};
        __half* dst = g_xa + row * KACT;
        #pragma unroll
        for (int j = 0; j < 4; j++) {
            int p = s_pos[c + j];
            if (p >= 0) dst[p] = __float2half_rn(vv[j]);
        }
    }
}

// ---------------- kernel 3: fp16 split of W*2048 ----------------
__global__ __launch_bounds__(256) void split_w_kernel(const float* __restrict__ W) {
    int i = blockIdx.x * blockDim.x + threadIdx.x;      // float4 index
    float4 v = ((const float4*)W)[i];
    float s0 = v.x * WSCALE, s1 = v.y * WSCALE, s2 = v.z * WSCALE, s3 = v.w * WSCALE;
    float h0 = __half2float(__float2half_rn(s0));
    float h1 = __half2float(__float2half_rn(s1));
    float h2 = __half2float(__float2half_rn(s2));
    float h3 = __half2float(__float2half_rn(s3));
    uint2 hp, lp;
    hp.x = pack_h2(h0, h1);            hp.y = pack_h2(h2, h3);
    lp.x = pack_h2(s0 - h0, s1 - h1);  lp.y = pack_h2(s2 - h2, s3 - h3);
    ((uint2*)g_wh)[i] = hp;
    ((uint2*)g_wl)[i] = lp;
}

// ---------------- kernel 4: fp16x2 mma GEMM + bias + scatter ----------------
extern __shared__ char dynsmem[];

__global__ __launch_bounds__(NTHREADS, 4)
void nsl_mma_gemm(const float* __restrict__ bias, const int* __restrict__ out_idx,
                  float* __restrict__ out) {
    __shared__ float s_bias[BN];
    __shared__ int   s_oidx[BN];

    const int tid  = threadIdx.x;
    const int wid  = tid >> 5;
    const int lane = tid & 31;
    const int wm   = wid & 1;         // 0..1 : 32-row band
    const int wn   = wid >> 1;        // 0..3 : 16-col band
    const int m0   = blockIdx.y * BM;
    const int n0   = blockIdx.x * BN;

    if (tid < BN) {
        s_oidx[tid] = __ldg(out_idx + n0 + tid);
        s_bias[tid] = __ldg(bias + n0 + tid);
    }

    const uint32_t sbase = (smem_u32(dynsmem) + 127) & ~127u;

    // per-thread load assignment: one 16B seg per plane per stage
    const int r = tid >> 2, p = tid & 3;
    const size_t goff = (size_t)r * KACT + p * 8;
    const __half* __restrict__ srcA  = g_xa + (size_t)m0 * KACT + goff;
    const __half* __restrict__ srcBh = g_wh + (size_t)n0 * KACT + goff;
    const __half* __restrict__ srcBl = g_wl + (size_t)n0 * KACT + goff;
    const uint32_t dsw = swz(r, p);

    auto load_stage = [&](int stage, int kc) {
        const uint32_t sb = sbase + stage * STAGE_BYTES + dsw;
        const int ko = kc * BKB;
        cp_async16(sb,                     srcA  + ko);
        cp_async16(sb + A_PLANE,           srcBh + ko);
        cp_async16(sb + A_PLANE + B_PLANE, srcBl + ko);
        asm volatile("cp.async.commit_group;");
    };

    // ldmatrix per-lane state
    const int lrow = lane & 15;
    const int hi   = lane >> 4;
    const int rot  = (lrow >> 1) & 3;
    const uint32_t ch[2] = { (uint32_t)(((0 + hi + rot) & 3) << 4),
                             (uint32_t)(((2 + hi + rot) & 3) << 4) };
    uint32_t aRow[2];
    #pragma unroll
    for (int f = 0; f < 2; f++)
        aRow[f] = (uint32_t)((wm * 32 + f * 16 + lrow) * 64);
    const uint32_t bRow = (uint32_t)(A_PLANE + (wn * 16 + lrow) * 64);

    float acc[2][2][4];
    #pragma unroll
    for (int i = 0; i < 2; i++)
        #pragma unroll
        for (int j = 0; j < 2; j++)
            #pragma unroll
            for (int q = 0; q < 4; q++) acc[i][j][q] = 0.f;

    load_stage(0, 0);
    load_stage(1, 1);

    for (int t = 0; t < NITER; t++) {
        if (t < NITER - 1) asm volatile("cp.async.wait_group 1;" ::: "memory");
        else               asm volatile("cp.async.wait_group 0;" ::: "memory");
        __syncthreads();
        // slot (t+2)%3 == (t-1)%3 was consumed last iteration -> safe to refill now
        if (t + 2 < NITER) load_stage((t + 2) % STAGES, t + 2);

        const uint32_t sb = sbase + (t % STAGES) * STAGE_BYTES;
        #pragma unroll
        for (int kk = 0; kk < 2; kk++) {            // 2 x k16 steps
            const uint32_t co = ch[kk];
            uint32_t a[2][4], bh[4], bl[4];
            ldsm4(a[0], sb + aRow[0] + co);
            ldsm4(a[1], sb + aRow[1] + co);
            ldsm4(bh,   sb + bRow + co);
            ldsm4(bl,   sb + B_PLANE + bRow + co);

            // term-major: hi term then lo term (8 MMAs per k-step)
            #pragma unroll
            for (int mi = 0; mi < 2; mi++) {
                mma_f16(acc[mi][0], a[mi], bh[0], bh[2]);
                mma_f16(acc[mi][1], a[mi], bh[1], bh[3]);
            }
            #pragma unroll
            for (int mi = 0; mi < 2; mi++) {
                mma_f16(acc[mi][0], a[mi], bl[0], bl[2]);
                mma_f16(acc[mi][1], a[mi], bl[1], bl[3]);
            }
        }
    }

    // ---- epilogue: unscale + bias + scatter ----
    const int rq = lane >> 2, cq = (lane & 3) * 2;
    #pragma unroll
    for (int mi = 0; mi < 2; mi++) {
        const int rbase = m0 + wm * 32 + mi * 16 + rq;
        float* __restrict__ row0 = out + (size_t)rbase * NFULL;
        float* __restrict__ row1 = row0 + (size_t)8 * NFULL;
        #pragma unroll
        for (int nf = 0; nf < 2; nf++) {
            const int nl = wn * 16 + nf * 8 + cq;
            const float* c = acc[mi][nf];
            row0[s_oidx[nl]]     = fmaf(c[0], INV_WSCALE, s_bias[nl]);
            row0[s_oidx[nl + 1]] = fmaf(c[1], INV_WSCALE, s_bias[nl + 1]);
            row1[s_oidx[nl]]     = fmaf(c[2], INV_WSCALE, s_bias[nl]);
            row1[s_oidx[nl + 1]] = fmaf(c[3], INV_WSCALE, s_bias[nl + 1]);
        }
    }
}

// ---------------- launch: fork-join across streams (graph-capturable) ----------------
extern "C" void kernel_launch(void* const* d_in, const int* in_sizes, int n_in,
                              void* d_out, int out_size) {
    const float* x       = (const float*)d_in[0];
    const float* W       = (const float*)d_in[1];
    const float* b       = (const float*)d_in[2];
    const int*   in_idx  = (const int*)d_in[3];
    const int*   out_idx = (const int*)d_in[4];
    float*       out     = (float*)d_out;

    static bool init_done = false;
    static cudaStream_t s1, s2;
    static cudaEvent_t  eFork, eMemset, eSplitW;
    if (!init_done) {
        cudaFuncSetAttribute(nsl_mma_gemm, cudaFuncAttributeMaxDynamicSharedMemorySize,
                             SMEM_BYTES + 128);
        cudaStreamCreateWithFlags(&s1, cudaStreamNonBlocking);
        cudaStreamCreateWithFlags(&s2, cudaStreamNonBlocking);
        cudaEventCreateWithFlags(&eFork,   cudaEventDisableTiming);
        cudaEventCreateWithFlags(&eMemset, cudaEventDisableTiming);
        cudaEventCreateWithFlags(&eSplitW, cudaEventDisableTiming);
        init_done = true;
    }

    // fork: s1 = memset (zero-fill output), s2 = split_w, main = build_pos -> gather
    cudaEventRecord(eFork, 0);
    cudaStreamWaitEvent(s1, eFork, 0);
    cudaStreamWaitEvent(s2, eFork, 0);

    cudaMemsetAsync(out, 0, (size_t)out_size * sizeof(float), s1);
    cudaEventRecord(eMemset, s1);

    split_w_kernel<<<(NACT * KACT / 4) / 256, 256, 0, s2>>>(W);
    cudaEventRecord(eSplitW, s2);

    build_pos_kernel<<<(NFULL + 255) / 256, 256>>>(in_idx);
    gather_kernel<<<MROWS / 4, 256>>>(x);

    // join: GEMM needs gather (stream 0), split_w (s2), memset (s1)
    cudaStreamWaitEvent(0, eMemset, 0);
    cudaStreamWaitEvent(0, eSplitW, 0);

    dim3 grid(NACT / BN, MROWS / BM);   // (16, 128) = 2048 CTAs
    nsl_mma_gemm<<<grid, NTHREADS, SMEM_BYTES + 128>>>(b, out_idx, out);
}

// round 11
// speedup vs baseline: 3.5386x; 1.1797x over previous
#include <cuda_runtime.h>
#include <cuda_fp16.h>
#include <cstdint>

// ---------------- problem constants ----------------
#define MROWS   8192
#define NFULL   4096
#define KACT    1024
#define NACT    1024

#define BM      64
#define BN      64
#define BKB     32                        // fp16 k-elements per stage chunk (64B/row)
#define NITER   (KACT / BKB)              // 32
#define STAGES  3
#define A_PLANE (64 * 64)                 // 4096 B (x fp16)
#define B_PLANE (64 * 64)                 // 4096 B (w hi / lo fp16)
#define STAGE_BYTES (A_PLANE + 2 * B_PLANE)       // 12288
#define SMEM_BYTES  (STAGES * STAGE_BYTES + 128)  // pipeline (reused as 16KB tile in epilogue)
#define NTHREADS 256

#define WSCALE     2048.0f
#define INV_WSCALE (1.0f / 2048.0f)

// scratch: gathered fp16 activations, split fp16 weights (x WSCALE), inverse maps
__device__ __half g_xa[(size_t)MROWS * KACT];
__device__ __half g_wh[(size_t)NACT * KACT];
__device__ __half g_wl[(size_t)NACT * KACT];
__device__ int    g_pos[NFULL];    // column -> position in in_idx  (-1 inactive)
__device__ int    g_opos[NFULL];   // column -> position in out_idx (-1 inactive)

// ---------------- helpers ----------------
__device__ __forceinline__ uint32_t smem_u32(const void* p) {
    uint32_t a;
    asm("{ .reg .u64 t; cvta.to.shared.u64 t, %1; cvt.u32.u64 %0, t; }" : "=r"(a) : "l"(p));
    return a;
}
__device__ __forceinline__ void cp_async16(uint32_t dst, const void* src) {
    asm volatile("cp.async.cg.shared.global [%0], [%1], 16;" :: "r"(dst), "l"(src));
}
__device__ __forceinline__ void ldsm4(uint32_t* r, uint32_t addr) {
    asm volatile("ldmatrix.sync.aligned.m8n8.x4.shared.b16 {%0,%1,%2,%3}, [%4];"
                 : "=r"(r[0]), "=r"(r[1]), "=r"(r[2]), "=r"(r[3]) : "r"(addr));
}
__device__ __forceinline__ void mma_f16(float* d, const uint32_t* a,
                                        uint32_t b0, uint32_t b1) {
    asm volatile(
        "mma.sync.aligned.m16n8k16.row.col.f32.f16.f16.f32 "
        "{%0,%1,%2,%3}, {%4,%5,%6,%7}, {%8,%9}, {%0,%1,%2,%3};"
        : "+f"(d[0]), "+f"(d[1]), "+f"(d[2]), "+f"(d[3])
        : "r"(a[0]), "r"(a[1]), "r"(a[2]), "r"(a[3]), "r"(b0), "r"(b1));
}
__device__ __forceinline__ uint32_t pack_h2(float a, float b) {
    __half2 t = __floats2half2_rn(a, b);
    return *reinterpret_cast<uint32_t*>(&t);
}
// swizzled 16B-chunk offset within a 64B-row plane
__device__ __forceinline__ uint32_t swz(int r, int p) {
    return (uint32_t)(r * 64 + (((p + (r >> 1)) & 3) << 4));
}
__device__ __forceinline__ int bsearch_idx(const int* __restrict__ idx, int c) {
    int lo = 0, hi = KACT - 1, found = -1;
    while (lo <= hi) {
        int mid = (lo + hi) >> 1;
        int v = __ldg(idx + mid);
        if (v == c) { found = mid; break; }
        if (v < c) lo = mid + 1; else hi = mid - 1;
    }
    return found;
}

// ---------------- kernel 1: inverse column maps ----------------
__global__ void build_maps_kernel(const int* __restrict__ in_idx,
                                  const int* __restrict__ out_idx) {
    int c = blockIdx.x * blockDim.x + threadIdx.x;
    if (c >= NFULL) return;
    g_pos[c]  = bsearch_idx(in_idx, c);
    g_opos[c] = bsearch_idx(out_idx, c);
}

// ---------------- kernel 2: gather x[:, in_idx] -> fp16, coalesced writes ----------------
__global__ __launch_bounds__(256) void gather_kernel(const float* __restrict__ x) {
    __shared__ int    s_pos[NFULL];          // 16 KB
    __shared__ __half s_stage[4 * KACT];     // 8 KB
    const int tid = threadIdx.x;
    for (int i = tid; i < NFULL; i += 256) s_pos[i] = g_pos[i];
    __syncthreads();

    const size_t r0 = (size_t)blockIdx.x * 4;
    const float4* __restrict__ x4 = (const float4*)x;
    #pragma unroll
    for (int i = 0; i < 16; i++) {
        int f = tid + i * 256;
        int rowl = f >> 10;
        int c4 = f & 1023;
        float4 v = x4[(r0 + rowl) * (NFULL / 4) + c4];
        int c = c4 * 4;
        float vv[4] = {v.x, v.y, v.z, v.w};
        #pragma unroll
        for (int j = 0; j < 4; j++) {
            int p = s_pos[c + j];
            if (p >= 0) s_stage[rowl * KACT + p] = __float2half_rn(vv[j]);
        }
    }
    __syncthreads();

    // write 4 rows x 1024 fp16 = 512 uint4, fully coalesced
    uint4* __restrict__ dst = (uint4*)(g_xa + r0 * KACT);
    const uint4* __restrict__ src = (const uint4*)s_stage;
    dst[tid]       = src[tid];
    dst[tid + 256] = src[tid + 256];
}

// ---------------- kernel 3: fp16 split of W*2048 ----------------
__global__ __launch_bounds__(256) void split_w_kernel(const float* __restrict__ W) {
    int i = blockIdx.x * blockDim.x + threadIdx.x;      // float4 index
    float4 v = ((const float4*)W)[i];
    float s0 = v.x * WSCALE, s1 = v.y * WSCALE, s2 = v.z * WSCALE, s3 = v.w * WSCALE;
    float h0 = __half2float(__float2half_rn(s0));
    float h1 = __half2float(__float2half_rn(s1));
    float h2 = __half2float(__float2half_rn(s2));
    float h3 = __half2float(__float2half_rn(s3));
    uint2 hp, lp;
    hp.x = pack_h2(h0, h1);            hp.y = pack_h2(h2, h3);
    lp.x = pack_h2(s0 - h0, s1 - h1);  lp.y = pack_h2(s2 - h2, s3 - h3);
    ((uint2*)g_wh)[i] = hp;
    ((uint2*)g_wl)[i] = lp;
}

// ---------------- kernel 4: fp16x2 mma GEMM + fused zero-fill/bias/scatter ----------------
extern __shared__ char dynsmem[];

__global__ __launch_bounds__(NTHREADS, 4)
void nsl_mma_gemm(const float* __restrict__ bias, const int* __restrict__ out_idx,
                  float* __restrict__ out) {
    __shared__ float s_bias[BN];

    const int tid  = threadIdx.x;
    const int wid  = tid >> 5;
    const int lane = tid & 31;
    const int wm   = wid & 1;         // 0..1 : 32-row band
    const int wn   = wid >> 1;        // 0..3 : 16-col band
    const int m0   = blockIdx.y * BM;
    const int n0   = blockIdx.x * BN; // local col block in [0, 1024)

    if (tid < BN) s_bias[tid] = __ldg(bias + n0 + tid);

    const uint32_t sbase = (smem_u32(dynsmem) + 127) & ~127u;

    // per-thread load assignment: one 16B seg per plane per stage
    const int r = tid >> 2, p = tid & 3;
    const size_t goff = (size_t)r * KACT + p * 8;
    const __half* __restrict__ srcA  = g_xa + (size_t)m0 * KACT + goff;
    const __half* __restrict__ srcBh = g_wh + (size_t)n0 * KACT + goff;
    const __half* __restrict__ srcBl = g_wl + (size_t)n0 * KACT + goff;
    const uint32_t dsw = swz(r, p);

    auto load_stage = [&](int stage, int kc) {
        const uint32_t sb = sbase + stage * STAGE_BYTES + dsw;
        const int ko = kc * BKB;
        cp_async16(sb,                     srcA  + ko);
        cp_async16(sb + A_PLANE,           srcBh + ko);
        cp_async16(sb + A_PLANE + B_PLANE, srcBl + ko);
        asm volatile("cp.async.commit_group;");
    };

    // ldmatrix per-lane state
    const int lrow = lane & 15;
    const int hi   = lane >> 4;
    const int rot  = (lrow >> 1) & 3;
    const uint32_t ch[2] = { (uint32_t)(((0 + hi + rot) & 3) << 4),
                             (uint32_t)(((2 + hi + rot) & 3) << 4) };
    uint32_t aRow[2];
    #pragma unroll
    for (int f = 0; f < 2; f++)
        aRow[f] = (uint32_t)((wm * 32 + f * 16 + lrow) * 64);
    const uint32_t bRow = (uint32_t)(A_PLANE + (wn * 16 + lrow) * 64);

    float acc[2][2][4];
    #pragma unroll
    for (int i = 0; i < 2; i++)
        #pragma unroll
        for (int j = 0; j < 2; j++)
            #pragma unroll
            for (int q = 0; q < 4; q++) acc[i][j][q] = 0.f;

    load_stage(0, 0);
    load_stage(1, 1);

    for (int t = 0; t < NITER; t++) {
        if (t < NITER - 1) asm volatile("cp.async.wait_group 1;" ::: "memory");
        else               asm volatile("cp.async.wait_group 0;" ::: "memory");
        __syncthreads();
        if (t + 2 < NITER) load_stage((t + 2) % STAGES, t + 2);

        const uint32_t sb = sbase + (t % STAGES) * STAGE_BYTES;
        #pragma unroll
        for (int kk = 0; kk < 2; kk++) {            // 2 x k16 steps
            const uint32_t co = ch[kk];
            uint32_t a[2][4], bh[4], bl[4];
            ldsm4(a[0], sb + aRow[0] + co);
            ldsm4(a[1], sb + aRow[1] + co);
            ldsm4(bh,   sb + bRow + co);
            ldsm4(bl,   sb + B_PLANE + bRow + co);

            #pragma unroll
            for (int mi = 0; mi < 2; mi++) {
                mma_f16(acc[mi][0], a[mi], bh[0], bh[2]);
                mma_f16(acc[mi][1], a[mi], bh[1], bh[3]);
            }
            #pragma unroll
            for (int mi = 0; mi < 2; mi++) {
                mma_f16(acc[mi][0], a[mi], bl[0], bl[2]);
                mma_f16(acc[mi][1], a[mi], bl[1], bl[3]);
            }
        }
    }

    // ---- epilogue: stage tile to smem, then ranged full-width write ----
    __syncthreads();                         // all LDSM reads of pipeline smem done
    float* stile = (float*)dynsmem;          // reuse pipeline smem: 64x64 fp32 = 16 KB

    const int rq = lane >> 2, cq = (lane & 3) * 2;
    #pragma unroll
    for (int mi = 0; mi < 2; mi++) {
        const int rb = wm * 32 + mi * 16 + rq;
        #pragma unroll
        for (int nf = 0; nf < 2; nf++) {
            const int nl = wn * 16 + nf * 8 + cq;
            const float* c = acc[mi][nf];
            stile[rb * BN + nl]           = c[0];
            stile[rb * BN + nl + 1]       = c[1];
            stile[(rb + 8) * BN + nl]     = c[2];
            stile[(rb + 8) * BN + nl + 1] = c[3];
        }
    }
    __syncthreads();

    // owned output-column range (out_idx sorted): [sBeg, sEnd)
    const int j = blockIdx.x;
    const int sBeg = (j == 0)             ? 0     : __ldg(out_idx + n0);
    const int sEnd = (j == NACT / BN - 1) ? NFULL : __ldg(out_idx + n0 + BN);

    for (int c = sBeg + tid; c < sEnd; c += NTHREADS) {
        const int pp  = __ldg(g_opos + c);           // >=0 iff active; then in [n0,n0+64)
        const bool act = (pp >= 0);
        const int nl  = act ? (pp - n0) : 0;
        const float bv = act ? s_bias[nl] : 0.f;
        float* __restrict__ ocol = out + (size_t)m0 * NFULL + c;
        #pragma unroll 8
        for (int m = 0; m < BM; m++) {
            float v = act ? fmaf(stile[m * BN + nl], INV_WSCALE, bv) : 0.f;
            ocol[(size_t)m * NFULL] = v;
        }
    }
}

// ---------------- launch ----------------
extern "C" void kernel_launch(void* const* d_in, const int* in_sizes, int n_in,
                              void* d_out, int out_size) {
    const float* x       = (const float*)d_in[0];
    const float* W       = (const float*)d_in[1];
    const float* b       = (const float*)d_in[2];
    const int*   in_idx  = (const int*)d_in[3];
    const int*   out_idx = (const int*)d_in[4];
    float*       out     = (float*)d_out;

    static bool attr_set = false;
    if (!attr_set) {
        cudaFuncSetAttribute(nsl_mma_gemm, cudaFuncAttributeMaxDynamicSharedMemorySize,
                             SMEM_BYTES);
        attr_set = true;
    }

    build_maps_kernel<<<(NFULL + 255) / 256, 256>>>(in_idx, out_idx);
    split_w_kernel<<<(NACT * KACT / 4) / 256, 256>>>(W);
    gather_kernel<<<MROWS / 4, 256>>>(x);

    dim3 grid(NACT / BN, MROWS / BM);   // (16, 128) = 2048 CTAs
    nsl_mma_gemm<<<grid, NTHREADS, SMEM_BYTES>>>(b, out_idx, out);
}

// round 12
// speedup vs baseline: 4.1773x; 1.1805x over previous
#include <cuda_runtime.h>
#include <cuda_fp16.h>
#include <cstdint>

// ---------------- problem constants ----------------
#define MROWS   8192
#define NFULL   4096
#define KACT    1024
#define NACT    1024

#define BM      64
#define BN      64
#define BKB     32                        // fp16 k-elements per stage chunk (64B/row)
#define NITER   (KACT / BKB)              // 32
#define STAGES  3
#define A_PLANE (64 * 64)                 // 4096 B (x fp16)
#define B_PLANE (64 * 64)                 // 4096 B (w fp16)
#define STAGE_BYTES (A_PLANE + B_PLANE)           // 8192
#define SMEM_BYTES  (STAGES * STAGE_BYTES + 128)  // 24704; epilogue tile 16KB fits
#define NTHREADS 256

#define WSCALE     2048.0f
#define INV_WSCALE (1.0f / 2048.0f)

// scratch: gathered fp16 activations, fp16 weights (x WSCALE), inverse maps
__device__ __half g_xa[(size_t)MROWS * KACT];
__device__ __half g_wf[(size_t)NACT * KACT];
__device__ int    g_pos[NFULL];    // column -> position in in_idx  (-1 inactive)
__device__ int    g_opos[NFULL];   // column -> position in out_idx (-1 inactive)

// ---------------- helpers ----------------
__device__ __forceinline__ uint32_t smem_u32(const void* p) {
    uint32_t a;
    asm("{ .reg .u64 t; cvta.to.shared.u64 t, %1; cvt.u32.u64 %0, t; }" : "=r"(a) : "l"(p));
    return a;
}
__device__ __forceinline__ void cp_async16(uint32_t dst, const void* src) {
    asm volatile("cp.async.cg.shared.global [%0], [%1], 16;" :: "r"(dst), "l"(src));
}
__device__ __forceinline__ void ldsm4(uint32_t* r, uint32_t addr) {
    asm volatile("ldmatrix.sync.aligned.m8n8.x4.shared.b16 {%0,%1,%2,%3}, [%4];"
                 : "=r"(r[0]), "=r"(r[1]), "=r"(r[2]), "=r"(r[3]) : "r"(addr));
}
__device__ __forceinline__ void mma_f16(float* d, const uint32_t* a,
                                        uint32_t b0, uint32_t b1) {
    asm volatile(
        "mma.sync.aligned.m16n8k16.row.col.f32.f16.f16.f32 "
        "{%0,%1,%2,%3}, {%4,%5,%6,%7}, {%8,%9}, {%0,%1,%2,%3};"
        : "+f"(d[0]), "+f"(d[1]), "+f"(d[2]), "+f"(d[3])
        : "r"(a[0]), "r"(a[1]), "r"(a[2]), "r"(a[3]), "r"(b0), "r"(b1));
}
__device__ __forceinline__ uint32_t pack_h2(float a, float b) {
    __half2 t = __floats2half2_rn(a, b);
    return *reinterpret_cast<uint32_t*>(&t);
}
// swizzled 16B-chunk offset within a 64B-row plane
__device__ __forceinline__ uint32_t swz(int r, int p) {
    return (uint32_t)(r * 64 + (((p + (r >> 1)) & 3) << 4));
}
__device__ __forceinline__ int bsearch_idx(const int* __restrict__ idx, int c) {
    int lo = 0, hi = KACT - 1, found = -1;
    while (lo <= hi) {
        int mid = (lo + hi) >> 1;
        int v = __ldg(idx + mid);
        if (v == c) { found = mid; break; }
        if (v < c) lo = mid + 1; else hi = mid - 1;
    }
    return found;
}

// ---------------- kernel 1: inverse column maps ----------------
__global__ void build_maps_kernel(const int* __restrict__ in_idx,
                                  const int* __restrict__ out_idx) {
    int c = blockIdx.x * blockDim.x + threadIdx.x;
    if (c >= NFULL) return;
    g_pos[c]  = bsearch_idx(in_idx, c);
    g_opos[c] = bsearch_idx(out_idx, c);
}

// ---------------- kernel 2: gather x[:, in_idx] -> fp16, coalesced writes ----------------
__global__ __launch_bounds__(256) void gather_kernel(const float* __restrict__ x) {
    __shared__ int    s_pos[NFULL];          // 16 KB
    __shared__ __half s_stage[4 * KACT];     // 8 KB
    const int tid = threadIdx.x;
    for (int i = tid; i < NFULL; i += 256) s_pos[i] = g_pos[i];
    __syncthreads();

    const size_t r0 = (size_t)blockIdx.x * 4;
    const float4* __restrict__ x4 = (const float4*)x;
    #pragma unroll
    for (int i = 0; i < 16; i++) {
        int f = tid + i * 256;
        int rowl = f >> 10;
        int c4 = f & 1023;
        float4 v = x4[(r0 + rowl) * (NFULL / 4) + c4];
        int c = c4 * 4;
        float vv[4] = {v.x, v.y, v.z, v.w};
        #pragma unroll
        for (int j = 0; j < 4; j++) {
            int p = s_pos[c + j];
            if (p >= 0) s_stage[rowl * KACT + p] = __float2half_rn(vv[j]);
        }
    }
    __syncthreads();

    // write 4 rows x 1024 fp16 = 512 uint4, fully coalesced
    uint4* __restrict__ dst = (uint4*)(g_xa + r0 * KACT);
    const uint4* __restrict__ src = (const uint4*)s_stage;
    dst[tid]       = src[tid];
    dst[tid + 256] = src[tid + 256];
}

// ---------------- kernel 3: W*2048 -> fp16 ----------------
__global__ __launch_bounds__(256) void conv_w_kernel(const float* __restrict__ W) {
    int i = blockIdx.x * blockDim.x + threadIdx.x;      // float4 index
    float4 v = ((const float4*)W)[i];
    uint2 hp;
    hp.x = pack_h2(v.x * WSCALE, v.y * WSCALE);
    hp.y = pack_h2(v.z * WSCALE, v.w * WSCALE);
    ((uint2*)g_wf)[i] = hp;
}

// ---------------- kernel 4: fp16 mma GEMM + fused zero-fill/bias/scatter ----------------
extern __shared__ char dynsmem[];

__global__ __launch_bounds__(NTHREADS, 4)
void nsl_mma_gemm(const float* __restrict__ bias, const int* __restrict__ out_idx,
                  float* __restrict__ out) {
    __shared__ float s_bias[BN];

    const int tid  = threadIdx.x;
    const int wid  = tid >> 5;
    const int lane = tid & 31;
    const int wm   = wid & 1;         // 0..1 : 32-row band
    const int wn   = wid >> 1;        // 0..3 : 16-col band
    const int m0   = blockIdx.y * BM;
    const int n0   = blockIdx.x * BN; // local col block in [0, 1024)

    if (tid < BN) s_bias[tid] = __ldg(bias + n0 + tid);

    const uint32_t sbase = (smem_u32(dynsmem) + 127) & ~127u;

    // per-thread load assignment: one 16B seg per plane per stage
    const int r = tid >> 2, p = tid & 3;
    const size_t goff = (size_t)r * KACT + p * 8;
    const __half* __restrict__ srcA = g_xa + (size_t)m0 * KACT + goff;
    const __half* __restrict__ srcB = g_wf + (size_t)n0 * KACT + goff;
    const uint32_t dsw = swz(r, p);

    auto load_stage = [&](int stage, int kc) {
        const uint32_t sb = sbase + stage * STAGE_BYTES + dsw;
        const int ko = kc * BKB;
        cp_async16(sb,           srcA + ko);
        cp_async16(sb + A_PLANE, srcB + ko);
        asm volatile("cp.async.commit_group;");
    };

    // ldmatrix per-lane state
    const int lrow = lane & 15;
    const int hi   = lane >> 4;
    const int rot  = (lrow >> 1) & 3;
    const uint32_t ch[2] = { (uint32_t)(((0 + hi + rot) & 3) << 4),
                             (uint32_t)(((2 + hi + rot) & 3) << 4) };
    uint32_t aRow[2];
    #pragma unroll
    for (int f = 0; f < 2; f++)
        aRow[f] = (uint32_t)((wm * 32 + f * 16 + lrow) * 64);
    const uint32_t bRow = (uint32_t)(A_PLANE + (wn * 16 + lrow) * 64);

    float acc[2][2][4];
    #pragma unroll
    for (int i = 0; i < 2; i++)
        #pragma unroll
        for (int j = 0; j < 2; j++)
            #pragma unroll
            for (int q = 0; q < 4; q++) acc[i][j][q] = 0.f;

    load_stage(0, 0);
    load_stage(1, 1);

    for (int t = 0; t < NITER; t++) {
        if (t < NITER - 1) asm volatile("cp.async.wait_group 1;" ::: "memory");
        else               asm volatile("cp.async.wait_group 0;" ::: "memory");
        __syncthreads();
        if (t + 2 < NITER) load_stage((t + 2) % STAGES, t + 2);

        const uint32_t sb = sbase + (t % STAGES) * STAGE_BYTES;
        #pragma unroll
        for (int kk = 0; kk < 2; kk++) {            // 2 x k16 steps
            const uint32_t co = ch[kk];
            uint32_t a[2][4], bf[4];
            ldsm4(a[0], sb + aRow[0] + co);
            ldsm4(a[1], sb + aRow[1] + co);
            ldsm4(bf,   sb + bRow + co);

            #pragma unroll
            for (int mi = 0; mi < 2; mi++) {
                mma_f16(acc[mi][0], a[mi], bf[0], bf[2]);
                mma_f16(acc[mi][1], a[mi], bf[1], bf[3]);
            }
        }
    }

    // ---- epilogue: stage tile to smem, then ranged full-width write ----
    __syncthreads();                         // all LDSM reads of pipeline smem done
    float* stile = (float*)dynsmem;          // reuse pipeline smem: 64x64 fp32 = 16 KB

    const int rq = lane >> 2, cq = (lane & 3) * 2;
    #pragma unroll
    for (int mi = 0; mi < 2; mi++) {
        const int rb = wm * 32 + mi * 16 + rq;
        #pragma unroll
        for (int nf = 0; nf < 2; nf++) {
            const int nl = wn * 16 + nf * 8 + cq;
            const float* c = acc[mi][nf];
            stile[rb * BN + nl]           = c[0];
            stile[rb * BN + nl + 1]       = c[1];
            stile[(rb + 8) * BN + nl]     = c[2];
            stile[(rb + 8) * BN + nl + 1] = c[3];
        }
    }
    __syncthreads();

    // owned output-column range (out_idx sorted): [sBeg, sEnd)
    const int j = blockIdx.x;
    const int sBeg = (j == 0)             ? 0     : __ldg(out_idx + n0);
    const int sEnd = (j == NACT / BN - 1) ? NFULL : __ldg(out_idx + n0 + BN);

    for (int c = sBeg + tid; c < sEnd; c += NTHREADS) {
        const int pp  = __ldg(g_opos + c);           // >=0 iff active; then in [n0,n0+64)
        const bool act = (pp >= 0);
        const int nl  = act ? (pp - n0) : 0;
        const float bv = act ? s_bias[nl] : 0.f;
        float* __restrict__ ocol = out + (size_t)m0 * NFULL + c;
        #pragma unroll 8
        for (int m = 0; m < BM; m++) {
            float v = act ? fmaf(stile[m * BN + nl], INV_WSCALE, bv) : 0.f;
            ocol[(size_t)m * NFULL] = v;
        }
    }
}

// ---------------- launch ----------------
extern "C" void kernel_launch(void* const* d_in, const int* in_sizes, int n_in,
                              void* d_out, int out_size) {
    const float* x       = (const float*)d_in[0];
    const float* W       = (const float*)d_in[1];
    const float* b       = (const float*)d_in[2];
    const int*   in_idx  = (const int*)d_in[3];
    const int*   out_idx = (const int*)d_in[4];
    float*       out     = (float*)d_out;

    static bool attr_set = false;
    if (!attr_set) {
        cudaFuncSetAttribute(nsl_mma_gemm, cudaFuncAttributeMaxDynamicSharedMemorySize,
                             SMEM_BYTES);
        attr_set = true;
    }

    build_maps_kernel<<<(NFULL + 255) / 256, 256>>>(in_idx, out_idx);
    conv_w_kernel<<<(NACT * KACT / 4) / 256, 256>>>(W);
    gather_kernel<<<MROWS / 4, 256>>>(x);

    dim3 grid(NACT / BN, MROWS / BM);   // (16, 128) = 2048 CTAs
    nsl_mma_gemm<<<grid, NTHREADS, SMEM_BYTES>>>(b, out_idx, out);
}

// round 13
// speedup vs baseline: 4.6029x; 1.1019x over previous
#include <cuda_runtime.h>
#include <cuda_fp16.h>
#include <cstdint>

// ---------------- problem constants ----------------
#define MROWS   8192
#define NFULL   4096
#define KACT    1024
#define NACT    1024

#define BM      128
#define BN      64
#define BKB     32                        // fp16 k-elements per stage chunk (64B/row)
#define NITER   (KACT / BKB)              // 32
#define STAGES  3
#define A_PLANE (128 * 64)                // 8192 B (x fp16)
#define B_PLANE (64 * 64)                 // 4096 B (w fp16)
#define STAGE_BYTES (A_PLANE + B_PLANE)           // 12288
#define SMEM_BYTES  (STAGES * STAGE_BYTES + 128)  // 36992; epilogue tile 32KB fits
#define NTHREADS 256

#define WSCALE     2048.0f
#define INV_WSCALE (1.0f / 2048.0f)

// scratch: gathered fp16 activations, fp16 weights (x WSCALE), inverse maps
__device__ __half g_xa[(size_t)MROWS * KACT];
__device__ __half g_wf[(size_t)NACT * KACT];
__device__ int    g_pos[NFULL];    // column -> position in in_idx  (-1 inactive)
__device__ int    g_opos[NFULL];   // column -> position in out_idx (-1 inactive)

// ---------------- helpers ----------------
__device__ __forceinline__ uint32_t smem_u32(const void* p) {
    uint32_t a;
    asm("{ .reg .u64 t; cvta.to.shared.u64 t, %1; cvt.u32.u64 %0, t; }" : "=r"(a) : "l"(p));
    return a;
}
__device__ __forceinline__ void cp_async16(uint32_t dst, const void* src) {
    asm volatile("cp.async.cg.shared.global [%0], [%1], 16;" :: "r"(dst), "l"(src));
}
__device__ __forceinline__ void ldsm4(uint32_t* r, uint32_t addr) {
    asm volatile("ldmatrix.sync.aligned.m8n8.x4.shared.b16 {%0,%1,%2,%3}, [%4];"
                 : "=r"(r[0]), "=r"(r[1]), "=r"(r[2]), "=r"(r[3]) : "r"(addr));
}
__device__ __forceinline__ void mma_f16(float* d, const uint32_t* a,
                                        uint32_t b0, uint32_t b1) {
    asm volatile(
        "mma.sync.aligned.m16n8k16.row.col.f32.f16.f16.f32 "
        "{%0,%1,%2,%3}, {%4,%5,%6,%7}, {%8,%9}, {%0,%1,%2,%3};"
        : "+f"(d[0]), "+f"(d[1]), "+f"(d[2]), "+f"(d[3])
        : "r"(a[0]), "r"(a[1]), "r"(a[2]), "r"(a[3]), "r"(b0), "r"(b1));
}
__device__ __forceinline__ uint32_t pack_h2(float a, float b) {
    __half2 t = __floats2half2_rn(a, b);
    return *reinterpret_cast<uint32_t*>(&t);
}
// swizzled 16B-chunk offset within a 64B-row plane
__device__ __forceinline__ uint32_t swz(int r, int p) {
    return (uint32_t)(r * 64 + (((p + (r >> 1)) & 3) << 4));
}
__device__ __forceinline__ int bsearch_idx(const int* __restrict__ idx, int c) {
    int lo = 0, hi = KACT - 1, found = -1;
    while (lo <= hi) {
        int mid = (lo + hi) >> 1;
        int v = __ldg(idx + mid);
        if (v == c) { found = mid; break; }
        if (v < c) lo = mid + 1; else hi = mid - 1;
    }
    return found;
}

// ---------------- kernel 1: inverse column maps ----------------
__global__ void build_maps_kernel(const int* __restrict__ in_idx,
                                  const int* __restrict__ out_idx) {
    int c = blockIdx.x * blockDim.x + threadIdx.x;
    if (c >= NFULL) return;
    g_pos[c]  = bsearch_idx(in_idx, c);
    g_opos[c] = bsearch_idx(out_idx, c);
}

// ---------------- kernel 2: gather x[:, in_idx] -> fp16, coalesced writes ----------------
__global__ __launch_bounds__(256) void gather_kernel(const float* __restrict__ x) {
    __shared__ int    s_pos[NFULL];          // 16 KB
    __shared__ __half s_stage[4 * KACT];     // 8 KB
    const int tid = threadIdx.x;
    for (int i = tid; i < NFULL; i += 256) s_pos[i] = g_pos[i];
    __syncthreads();

    const size_t r0 = (size_t)blockIdx.x * 4;
    const float4* __restrict__ x4 = (const float4*)x;
    #pragma unroll
    for (int i = 0; i < 16; i++) {
        int f = tid + i * 256;
        int rowl = f >> 10;
        int c4 = f & 1023;
        float4 v = x4[(r0 + rowl) * (NFULL / 4) + c4];
        int c = c4 * 4;
        float vv[4] = {v.x, v.y, v.z, v.w};
        #pragma unroll
        for (int j = 0; j < 4; j++) {
            int p = s_pos[c + j];
            if (p >= 0) s_stage[rowl * KACT + p] = __float2half_rn(vv[j]);
        }
    }
    __syncthreads();

    // write 4 rows x 1024 fp16 = 512 uint4, fully coalesced
    uint4* __restrict__ dst = (uint4*)(g_xa + r0 * KACT);
    const uint4* __restrict__ src = (const uint4*)s_stage;
    dst[tid]       = src[tid];
    dst[tid + 256] = src[tid + 256];
}

// ---------------- kernel 3: W*2048 -> fp16 ----------------
__global__ __launch_bounds__(256) void conv_w_kernel(const float* __restrict__ W) {
    int i = blockIdx.x * blockDim.x + threadIdx.x;      // float4 index
    float4 v = ((const float4*)W)[i];
    uint2 hp;
    hp.x = pack_h2(v.x * WSCALE, v.y * WSCALE);
    hp.y = pack_h2(v.z * WSCALE, v.w * WSCALE);
    ((uint2*)g_wf)[i] = hp;
}

// ---------------- kernel 4: fp16 mma GEMM + fused zero-fill/bias/scatter ----------------
extern __shared__ char dynsmem[];

__global__ __launch_bounds__(NTHREADS, 3)
void nsl_mma_gemm(const float* __restrict__ bias, const int* __restrict__ out_idx,
                  float* __restrict__ out) {
    __shared__ float s_bias[BN];

    const int tid  = threadIdx.x;
    const int wid  = tid >> 5;
    const int lane = tid & 31;
    const int wm   = wid & 3;         // 0..3 : 32-row band
    const int wn   = wid >> 2;        // 0..1 : 32-col band
    const int m0   = blockIdx.y * BM;
    const int n0   = blockIdx.x * BN; // local col block in [0, 1024)

    if (tid < BN) s_bias[tid] = __ldg(bias + n0 + tid);

    const uint32_t sbase = (smem_u32(dynsmem) + 127) & ~127u;

    // per-thread load assignment: A 512 segs (2/thread), B 256 segs (1/thread)
    const int r = tid >> 2, p = tid & 3;
    const __half* __restrict__ srcA = g_xa + (size_t)m0 * KACT + (size_t)r * KACT + p * 8;
    const __half* __restrict__ srcB = g_wf + (size_t)n0 * KACT + (size_t)r * KACT + p * 8;
    const uint32_t dswA0 = swz(r, p);
    const uint32_t dswA1 = swz(r + 64, p);
    const uint32_t dswB  = swz(r, p);

    auto load_stage = [&](int stage, int kc) {
        const uint32_t sb = sbase + stage * STAGE_BYTES;
        const int ko = kc * BKB;
        cp_async16(sb + dswA0,           srcA + ko);
        cp_async16(sb + dswA1,           srcA + (size_t)64 * KACT + ko);
        cp_async16(sb + A_PLANE + dswB,  srcB + ko);
        asm volatile("cp.async.commit_group;");
    };

    // ldmatrix per-lane state
    const int lrow = lane & 15;
    const int hi   = lane >> 4;
    const int rot  = (lrow >> 1) & 3;
    const uint32_t ch[2] = { (uint32_t)(((0 + hi + rot) & 3) << 4),
                             (uint32_t)(((2 + hi + rot) & 3) << 4) };
    uint32_t aRow[2], bRow[2];
    #pragma unroll
    for (int f = 0; f < 2; f++)
        aRow[f] = (uint32_t)((wm * 32 + f * 16 + lrow) * 64);
    #pragma unroll
    for (int q = 0; q < 2; q++)
        bRow[q] = (uint32_t)(A_PLANE + (wn * 32 + q * 16 + lrow) * 64);

    float acc[2][4][4];
    #pragma unroll
    for (int i = 0; i < 2; i++)
        #pragma unroll
        for (int j = 0; j < 4; j++)
            #pragma unroll
            for (int q = 0; q < 4; q++) acc[i][j][q] = 0.f;

    load_stage(0, 0);
    load_stage(1, 1);

    for (int t = 0; t < NITER; t++) {
        if (t < NITER - 1) asm volatile("cp.async.wait_group 1;" ::: "memory");
        else               asm volatile("cp.async.wait_group 0;" ::: "memory");
        __syncthreads();
        if (t + 2 < NITER) load_stage((t + 2) % STAGES, t + 2);

        const uint32_t sb = sbase + (t % STAGES) * STAGE_BYTES;
        #pragma unroll
        for (int kk = 0; kk < 2; kk++) {            // 2 x k16 steps
            const uint32_t co = ch[kk];
            uint32_t a[2][4], bf[2][4];
            ldsm4(a[0],  sb + aRow[0] + co);
            ldsm4(a[1],  sb + aRow[1] + co);
            ldsm4(bf[0], sb + bRow[0] + co);
            ldsm4(bf[1], sb + bRow[1] + co);

            #pragma unroll
            for (int mi = 0; mi < 2; mi++)
                #pragma unroll
                for (int q = 0; q < 2; q++) {
                    mma_f16(acc[mi][2 * q + 0], a[mi], bf[q][0], bf[q][2]);
                    mma_f16(acc[mi][2 * q + 1], a[mi], bf[q][1], bf[q][3]);
                }
        }
    }

    // ---- epilogue: stage tile to smem, then ranged full-width write ----
    __syncthreads();                         // all LDSM reads of pipeline smem done
    float* stile = (float*)dynsmem;          // reuse pipeline smem: 128x64 fp32 = 32 KB

    const int rq = lane >> 2, cq = (lane & 3) * 2;
    #pragma unroll
    for (int mi = 0; mi < 2; mi++) {
        const int rb = wm * 32 + mi * 16 + rq;
        #pragma unroll
        for (int nf = 0; nf < 4; nf++) {
            const int nl = wn * 32 + nf * 8 + cq;
            const float* c = acc[mi][nf];
            stile[rb * BN + nl]           = c[0];
            stile[rb * BN + nl + 1]       = c[1];
            stile[(rb + 8) * BN + nl]     = c[2];
            stile[(rb + 8) * BN + nl + 1] = c[3];
        }
    }
    __syncthreads();

    // owned output-column range (out_idx sorted): [sBeg, sEnd)
    const int j = blockIdx.x;
    const int sBeg = (j == 0)             ? 0     : __ldg(out_idx + n0);
    const int sEnd = (j == NACT / BN - 1) ? NFULL : __ldg(out_idx + n0 + BN);

    for (int c = sBeg + tid; c < sEnd; c += NTHREADS) {
        const int pp  = __ldg(g_opos + c);           // >=0 iff active; then in [n0,n0+64)
        const bool act = (pp >= 0);
        const int nl  = act ? (pp - n0) : 0;
        const float bv = act ? s_bias[nl] : 0.f;
        float* __restrict__ ocol = out + (size_t)m0 * NFULL + c;
        #pragma unroll 8
        for (int m = 0; m < BM; m++) {
            float v = act ? fmaf(stile[m * BN + nl], INV_WSCALE, bv) : 0.f;
            ocol[(size_t)m * NFULL] = v;
        }
    }
}

// ---------------- launch ----------------
extern "C" void kernel_launch(void* const* d_in, const int* in_sizes, int n_in,
                              void* d_out, int out_size) {
    const float* x       = (const float*)d_in[0];
    const float* W       = (const float*)d_in[1];
    const float* b       = (const float*)d_in[2];
    const int*   in_idx  = (const int*)d_in[3];
    const int*   out_idx = (const int*)d_in[4];
    float*       out     = (float*)d_out;

    static bool attr_set = false;
    if (!attr_set) {
        cudaFuncSetAttribute(nsl_mma_gemm, cudaFuncAttributeMaxDynamicSharedMemorySize,
                             SMEM_BYTES);
        attr_set = true;
    }

    build_maps_kernel<<<(NFULL + 255) / 256, 256>>>(in_idx, out_idx);
    conv_w_kernel<<<(NACT * KACT / 4) / 256, 256>>>(W);
    gather_kernel<<<MROWS / 4, 256>>>(x);

    dim3 grid(NACT / BN, MROWS / BM);   // (16, 64) = 1024 CTAs
    nsl_mma_gemm<<<grid, NTHREADS, SMEM_BYTES>>>(b, out_idx, out);
}